// round 1
// baseline (speedup 1.0000x reference)
#include <cuda_runtime.h>
#include <cstdio>

// Problem constants (from reference): N=100000, E=1.6M, EL=200000
#define NMAX 100000
#define KDIM 128

// Scratch (static __device__ arrays — no allocation allowed)
__device__ float g_deg[NMAX];            // deg -> dis (in place)
__device__ float g_h[NMAX * 128];        // pre-aggregation features h = in @ W
__device__ float g_bufA[NMAX * 128];     // layer outputs (ping)
__device__ float g_bufB[NMAX * 128];     // layer outputs (pong)

// ---------------------------------------------------------------------------
// Degree / normalization
// ---------------------------------------------------------------------------
__global__ void deg_init_kernel(float* __restrict__ deg, int n) {
    int i = blockIdx.x * blockDim.x + threadIdx.x;
    if (i < n) deg[i] = 1.0f;   // self-loop contributes 1 to every node's degree
}

__global__ void deg_acc_kernel(float* __restrict__ deg, const int* __restrict__ dst, int E) {
    int e = blockIdx.x * blockDim.x + threadIdx.x;
    if (e < E) atomicAdd(&deg[dst[e]], 1.0f);
}

__global__ void dis_kernel(float* __restrict__ deg, int n) {
    int i = blockIdx.x * blockDim.x + threadIdx.x;
    if (i < n) deg[i] = rsqrtf(deg[i]);  // deg >= 1 always (self-loops)
}

// ---------------------------------------------------------------------------
// GEMM: h = relu?(in) @ W ; out_init = dis[i]^2 * h[i] + b   (self-loop + bias)
// Block: 256 threads, 64 rows, full K=128. W + X tile staged in dynamic smem.
// ---------------------------------------------------------------------------
template <int DOUT, bool RELU_IN>
__global__ void __launch_bounds__(256)
gemm_kernel(const float* __restrict__ in, const float* __restrict__ W,
            const float* __restrict__ bias, const float* __restrict__ dis,
            float* __restrict__ h, float* __restrict__ out, int n)
{
    constexpr int ROWS = 64;
    constexpr int THREADS = 256;
    constexpr int CG = DOUT / 4;          // float4 column groups
    constexpr int RSUB = THREADS / CG;    // row sub-partitions
    constexpr int RPT = ROWS / RSUB;      // rows per thread

    extern __shared__ float smem[];
    float* sW = smem;                     // [KDIM * DOUT]
    float* sX = smem + KDIM * DOUT;       // [ROWS * KDIM]

    const int t = threadIdx.x;
    const int row0 = blockIdx.x * ROWS;

    // Stage W
    const float4* W4 = reinterpret_cast<const float4*>(W);
    float4* sW4 = reinterpret_cast<float4*>(sW);
    #pragma unroll
    for (int i = t; i < KDIM * DOUT / 4; i += THREADS) sW4[i] = W4[i];

    // Stage X tile (with optional ReLU folded into the load)
    const float4* in4 = reinterpret_cast<const float4*>(in);
    float4* sX4 = reinterpret_cast<float4*>(sX);
    #pragma unroll
    for (int i = t; i < ROWS * KDIM / 4; i += THREADS) {
        int r = i / (KDIM / 4);
        int c = i % (KDIM / 4);
        int gr = row0 + r;
        float4 v = make_float4(0.f, 0.f, 0.f, 0.f);
        if (gr < n) v = in4[(size_t)gr * (KDIM / 4) + c];
        if (RELU_IN) {
            v.x = fmaxf(v.x, 0.f); v.y = fmaxf(v.y, 0.f);
            v.z = fmaxf(v.z, 0.f); v.w = fmaxf(v.w, 0.f);
        }
        sX4[i] = v;
    }
    __syncthreads();

    const int c  = t % CG;
    const int rs = t / CG;

    float4 acc[RPT];
    #pragma unroll
    for (int j = 0; j < RPT; ++j) acc[j] = make_float4(0.f, 0.f, 0.f, 0.f);

    #pragma unroll 8
    for (int k = 0; k < KDIM; ++k) {
        float4 w = sW4[k * CG + c];
        #pragma unroll
        for (int j = 0; j < RPT; ++j) {
            float xv = sX[(rs + j * RSUB) * KDIM + k];
            acc[j].x = fmaf(xv, w.x, acc[j].x);
            acc[j].y = fmaf(xv, w.y, acc[j].y);
            acc[j].z = fmaf(xv, w.z, acc[j].z);
            acc[j].w = fmaf(xv, w.w, acc[j].w);
        }
    }

    float4 b4 = reinterpret_cast<const float4*>(bias)[c];
    #pragma unroll
    for (int j = 0; j < RPT; ++j) {
        int gr = row0 + rs + j * RSUB;
        if (gr < n) {
            float d = dis[gr];
            float dd = d * d;
            float4 a = acc[j];
            reinterpret_cast<float4*>(h)[(size_t)gr * CG + c] = a;
            float4 o;
            o.x = fmaf(a.x, dd, b4.x);
            o.y = fmaf(a.y, dd, b4.y);
            o.z = fmaf(a.z, dd, b4.z);
            o.w = fmaf(a.w, dd, b4.w);
            reinterpret_cast<float4*>(out)[(size_t)gr * CG + c] = o;
        }
    }
}

// ---------------------------------------------------------------------------
// Scatter: out[dst] += dis[src]*dis[dst] * h[src]   via red.global.add.v4.f32
// D/4 lanes per edge, each lane one float4.
// ---------------------------------------------------------------------------
template <int D>
__global__ void __launch_bounds__(256)
scatter_kernel(const int* __restrict__ src, const int* __restrict__ dst,
               const float* __restrict__ dis, const float* __restrict__ h,
               float* __restrict__ out, int E)
{
    constexpr int LPE = D / 4;  // lanes per edge (32 for D=128, 16 for D=64)
    int tid = blockIdx.x * blockDim.x + threadIdx.x;
    int eid = tid / LPE;
    int li  = tid % LPE;
    if (eid >= E) return;

    int s = src[eid];
    int d = dst[eid];
    float w = dis[s] * dis[d];

    float4 v = reinterpret_cast<const float4*>(h)[(size_t)s * LPE + li];
    v.x *= w; v.y *= w; v.z *= w; v.w *= w;

    float* p = out + (size_t)d * D + li * 4;
    asm volatile("red.global.add.v4.f32 [%0], {%1, %2, %3, %4};"
                 :: "l"(p), "f"(v.x), "f"(v.y), "f"(v.z), "f"(v.w)
                 : "memory");
}

// ---------------------------------------------------------------------------
// Decode: hidden = z[s]*z[t]; logits = sum(hidden); hidden_n = hidden/||hidden||
// 16 lanes per label-edge (64 floats = 16 x float4/lane... 4 floats per lane).
// ---------------------------------------------------------------------------
__global__ void __launch_bounds__(256)
decode_kernel(const float* __restrict__ z, const int* __restrict__ eli,
              float* __restrict__ outh, float* __restrict__ outl, int EL)
{
    int tid = blockIdx.x * blockDim.x + threadIdx.x;
    int eid = tid >> 4;       // 16 lanes per edge
    int li  = tid & 15;
    int lane = threadIdx.x & 31;
    unsigned mask = 0xFFFFu << (lane & 16);   // group-local mask (lanes 0-15 / 16-31)

    if (eid >= EL) return;    // eid uniform within each 16-lane group

    int s = eli[eid];
    int t = eli[EL + eid];
    const float4* z4 = reinterpret_cast<const float4*>(z);
    float4 a = z4[(size_t)s * 16 + li];
    float4 b = z4[(size_t)t * 16 + li];

    float4 hh;
    hh.x = a.x * b.x; hh.y = a.y * b.y; hh.z = a.z * b.z; hh.w = a.w * b.w;

    float sum = hh.x + hh.y + hh.z + hh.w;
    float sq  = hh.x * hh.x + hh.y * hh.y + hh.z * hh.z + hh.w * hh.w;

    #pragma unroll
    for (int off = 8; off > 0; off >>= 1) {
        sum += __shfl_xor_sync(mask, sum, off);
        sq  += __shfl_xor_sync(mask, sq,  off);
    }

    float nrm = sqrtf(sq);
    float inv = 1.0f / fmaxf(nrm, 1e-12f);
    float4 o;
    o.x = hh.x * inv; o.y = hh.y * inv; o.z = hh.z * inv; o.w = hh.w * inv;
    reinterpret_cast<float4*>(outh)[(size_t)eid * 16 + li] = o;
    if (li == 0) outl[eid] = sum;
}

// ---------------------------------------------------------------------------
// Launch
// ---------------------------------------------------------------------------
extern "C" void kernel_launch(void* const* d_in, const int* in_sizes, int n_in,
                              void* d_out, int out_size)
{
    const float* x   = (const float*)d_in[0];
    const float* W1  = (const float*)d_in[1];
    const float* b1  = (const float*)d_in[2];
    const float* W2  = (const float*)d_in[3];
    const float* b2  = (const float*)d_in[4];
    const float* W3  = (const float*)d_in[5];
    const float* b3  = (const float*)d_in[6];
    const int*   ei  = (const int*)d_in[7];
    const int*   eli = (const int*)d_in[8];

    const int n  = in_sizes[0] / 128;
    const int E  = in_sizes[7] / 2;
    const int EL = in_sizes[8] / 2;

    float* out = (float*)d_out;
    float* out_hidden = out;
    float* out_logits = out + (size_t)EL * 64;

    float *d_deg, *d_h, *d_bufA, *d_bufB;
    cudaGetSymbolAddress((void**)&d_deg,  g_deg);
    cudaGetSymbolAddress((void**)&d_h,    g_h);
    cudaGetSymbolAddress((void**)&d_bufA, g_bufA);
    cudaGetSymbolAddress((void**)&d_bufB, g_bufB);

    // Dynamic smem opt-in (idempotent)
    cudaFuncSetAttribute(gemm_kernel<128, false>, cudaFuncAttributeMaxDynamicSharedMemorySize, 98304);
    cudaFuncSetAttribute(gemm_kernel<128, true>,  cudaFuncAttributeMaxDynamicSharedMemorySize, 98304);
    cudaFuncSetAttribute(gemm_kernel<64,  true>,  cudaFuncAttributeMaxDynamicSharedMemorySize, 65536);

    const int* src = ei;
    const int* dst = ei + E;

    // 1. dis = rsqrt(deg)
    deg_init_kernel<<<(n + 255) / 256, 256>>>(d_deg, n);
    deg_acc_kernel<<<(E + 255) / 256, 256>>>(d_deg, dst, E);
    dis_kernel<<<(n + 255) / 256, 256>>>(d_deg, n);

    const int gemm_blocks = (n + 63) / 64;
    const int sc128_blocks = ((E * 32) + 255) / 256;
    const int sc64_blocks  = ((E * 16) + 255) / 256;

    // Layer 1: h = x @ W1 ; z1 = scatter + self-loop + b1   (ReLU deferred)
    gemm_kernel<128, false><<<gemm_blocks, 256, 98304>>>(x, W1, b1, d_deg, d_h, d_bufA, n);
    scatter_kernel<128><<<sc128_blocks, 256>>>(src, dst, d_deg, d_h, d_bufA, E);

    // Layer 2: h = relu(z1) @ W2 ; z2 = ...
    gemm_kernel<128, true><<<gemm_blocks, 256, 98304>>>(d_bufA, W2, b2, d_deg, d_h, d_bufB, n);
    scatter_kernel<128><<<sc128_blocks, 256>>>(src, dst, d_deg, d_h, d_bufB, E);

    // Layer 3 (DOUT=64, no output ReLU): z3 = ...
    gemm_kernel<64, true><<<gemm_blocks, 256, 65536>>>(d_bufB, W3, b3, d_deg, d_h, d_bufA, n);
    scatter_kernel<64><<<sc64_blocks, 256>>>(src, dst, d_deg, d_h, d_bufA, E);

    // Decode
    decode_kernel<<<((EL * 16) + 255) / 256, 256>>>(d_bufA, eli, out_hidden, out_logits, EL);
}

// round 2
// speedup vs baseline: 1.6550x; 1.6550x over previous
#include <cuda_runtime.h>
#include <cstdio>

// Problem constants (from reference): N=100000, E=1.6M, EL=200000
#define NMAX 100000
#define EMAX 1600000
#define KDIM 128

// Scratch (static __device__ arrays — no allocation allowed)
__device__ float g_dis[NMAX];             // d^-1/2
__device__ int   g_cnt[NMAX];             // in-degree histogram (excl self-loop)
__device__ int   g_rowptr[NMAX + 1];      // CSR row pointers (by dst)
__device__ int   g_cursor[NMAX];          // fill cursors
__device__ int   g_bsums[1024];           // scan block sums
__device__ int   g_esrc[EMAX];            // CSR: src node per slot
__device__ float g_ewt[EMAX];             // CSR: edge weight dis[s]*dis[d]
__device__ float g_h[NMAX * 128];         // pre-aggregation features h = in @ W
__device__ float g_bufA[NMAX * 128];      // layer outputs (ping)
__device__ float g_bufB[NMAX * 128];      // layer outputs (pong)

// ---------------------------------------------------------------------------
// CSR build: histogram -> dis -> scan -> fill
// ---------------------------------------------------------------------------
__global__ void zero_cnt_kernel(int* __restrict__ cnt, int n) {
    int i = blockIdx.x * blockDim.x + threadIdx.x;
    if (i < n) cnt[i] = 0;
}

__global__ void count_kernel(int* __restrict__ cnt, const int* __restrict__ dst, int E) {
    int e = blockIdx.x * blockDim.x + threadIdx.x;
    if (e < E) atomicAdd(&cnt[dst[e]], 1);
}

__global__ void dis_kernel(const int* __restrict__ cnt, float* __restrict__ dis, int n) {
    int i = blockIdx.x * blockDim.x + threadIdx.x;
    if (i < n) dis[i] = rsqrtf((float)(cnt[i] + 1));   // +1 self-loop; deg >= 1 always
}

// Exclusive scan, step 1: per-block (256) scan, emit block totals.
__global__ void scan1_kernel(const int* __restrict__ cnt, int* __restrict__ part,
                             int* __restrict__ sums, int n) {
    __shared__ int sm[256];
    int t = threadIdx.x;
    int i = blockIdx.x * 256 + t;
    int v = (i < n) ? cnt[i] : 0;
    sm[t] = v;
    __syncthreads();
    #pragma unroll
    for (int off = 1; off < 256; off <<= 1) {
        int a = (t >= off) ? sm[t - off] : 0;
        __syncthreads();
        sm[t] += a;
        __syncthreads();
    }
    if (i < n) part[i] = sm[t] - v;          // exclusive within block
    if (t == 255) sums[blockIdx.x] = sm[255];
}

// Step 2: single-block scan of block totals (nb <= 1024).
__global__ void scan2_kernel(int* __restrict__ sums, int nb) {
    __shared__ int sm[1024];
    int t = threadIdx.x;
    int v = (t < nb) ? sums[t] : 0;
    sm[t] = v;
    __syncthreads();
    #pragma unroll
    for (int off = 1; off < 1024; off <<= 1) {
        int a = (t >= off) ? sm[t - off] : 0;
        __syncthreads();
        sm[t] += a;
        __syncthreads();
    }
    if (t < nb) sums[t] = sm[t] - v;          // exclusive block offsets
}

// Step 3: combine, write row_ptr + cursor.
__global__ void scan3_kernel(const int* __restrict__ part, const int* __restrict__ sums,
                             int* __restrict__ row_ptr, int* __restrict__ cursor,
                             int n, int E) {
    int i = blockIdx.x * blockDim.x + threadIdx.x;
    if (i < n) {
        int v = part[i] + sums[i >> 8];
        row_ptr[i] = v;
        cursor[i] = v;
    }
    if (i == 0) row_ptr[n] = E;
}

__global__ void fill_kernel(const int* __restrict__ src, const int* __restrict__ dst,
                            const float* __restrict__ dis,
                            int* __restrict__ cursor, int* __restrict__ esrc,
                            float* __restrict__ ewt, int E) {
    int e = blockIdx.x * blockDim.x + threadIdx.x;
    if (e >= E) return;
    int s = src[e];
    int d = dst[e];
    int pos = atomicAdd(&cursor[d], 1);
    esrc[pos] = s;
    ewt[pos] = dis[s] * dis[d];
}

// ---------------------------------------------------------------------------
// GEMM: h = relu?(in) @ W ; out_init = dis[i]^2 * h[i] + b   (self-loop + bias)
// ---------------------------------------------------------------------------
template <int DOUT, bool RELU_IN>
__global__ void __launch_bounds__(256)
gemm_kernel(const float* __restrict__ in, const float* __restrict__ W,
            const float* __restrict__ bias, const float* __restrict__ dis,
            float* __restrict__ h, float* __restrict__ out, int n)
{
    constexpr int ROWS = 64;
    constexpr int THREADS = 256;
    constexpr int CG = DOUT / 4;          // float4 column groups
    constexpr int RSUB = THREADS / CG;    // row sub-partitions
    constexpr int RPT = ROWS / RSUB;      // rows per thread

    extern __shared__ float smem[];
    float* sW = smem;                     // [KDIM * DOUT]
    float* sX = smem + KDIM * DOUT;       // [ROWS * KDIM]

    const int t = threadIdx.x;
    const int row0 = blockIdx.x * ROWS;

    const float4* W4 = reinterpret_cast<const float4*>(W);
    float4* sW4 = reinterpret_cast<float4*>(sW);
    #pragma unroll
    for (int i = t; i < KDIM * DOUT / 4; i += THREADS) sW4[i] = W4[i];

    const float4* in4 = reinterpret_cast<const float4*>(in);
    float4* sX4 = reinterpret_cast<float4*>(sX);
    #pragma unroll
    for (int i = t; i < ROWS * KDIM / 4; i += THREADS) {
        int r = i / (KDIM / 4);
        int c = i % (KDIM / 4);
        int gr = row0 + r;
        float4 v = make_float4(0.f, 0.f, 0.f, 0.f);
        if (gr < n) v = in4[(size_t)gr * (KDIM / 4) + c];
        if (RELU_IN) {
            v.x = fmaxf(v.x, 0.f); v.y = fmaxf(v.y, 0.f);
            v.z = fmaxf(v.z, 0.f); v.w = fmaxf(v.w, 0.f);
        }
        sX4[i] = v;
    }
    __syncthreads();

    const int c  = t % CG;
    const int rs = t / CG;

    float4 acc[RPT];
    #pragma unroll
    for (int j = 0; j < RPT; ++j) acc[j] = make_float4(0.f, 0.f, 0.f, 0.f);

    #pragma unroll 8
    for (int k = 0; k < KDIM; ++k) {
        float4 w = sW4[k * CG + c];
        #pragma unroll
        for (int j = 0; j < RPT; ++j) {
            float xv = sX[(rs + j * RSUB) * KDIM + k];
            acc[j].x = fmaf(xv, w.x, acc[j].x);
            acc[j].y = fmaf(xv, w.y, acc[j].y);
            acc[j].z = fmaf(xv, w.z, acc[j].z);
            acc[j].w = fmaf(xv, w.w, acc[j].w);
        }
    }

    float4 b4 = reinterpret_cast<const float4*>(bias)[c];
    #pragma unroll
    for (int j = 0; j < RPT; ++j) {
        int gr = row0 + rs + j * RSUB;
        if (gr < n) {
            float d = dis[gr];
            float dd = d * d;
            float4 a = acc[j];
            reinterpret_cast<float4*>(h)[(size_t)gr * CG + c] = a;
            float4 o;
            o.x = fmaf(a.x, dd, b4.x);
            o.y = fmaf(a.y, dd, b4.y);
            o.z = fmaf(a.z, dd, b4.z);
            o.w = fmaf(a.w, dd, b4.w);
            reinterpret_cast<float4*>(out)[(size_t)gr * CG + c] = o;
        }
    }
}

// ---------------------------------------------------------------------------
// CSR gather-aggregate: out[v] += sum_{e in in(v)} ewt[e] * h[esrc[e]]
// One D/4-lane group per node; 4-edge software pipeline for MLP.
// ---------------------------------------------------------------------------
template <int D>
__global__ void __launch_bounds__(256)
agg_kernel(const int* __restrict__ rp, const int* __restrict__ esrc,
           const float* __restrict__ ewt, const float* __restrict__ h,
           float* __restrict__ out, int n)
{
    constexpr int G = D / 4;
    int tid = blockIdx.x * blockDim.x + threadIdx.x;
    int node = tid / G;
    int li   = tid % G;
    if (node >= n) return;

    int beg = rp[node];
    int end = rp[node + 1];

    const float4* h4 = reinterpret_cast<const float4*>(h);
    float4* out4 = reinterpret_cast<float4*>(out);
    float4 acc = out4[(size_t)node * G + li];   // self-loop + bias already there

    int j = beg;
    for (; j + 4 <= end; j += 4) {
        int s0 = esrc[j], s1 = esrc[j + 1], s2 = esrc[j + 2], s3 = esrc[j + 3];
        float w0 = ewt[j], w1 = ewt[j + 1], w2 = ewt[j + 2], w3 = ewt[j + 3];
        float4 v0 = h4[(size_t)s0 * G + li];
        float4 v1 = h4[(size_t)s1 * G + li];
        float4 v2 = h4[(size_t)s2 * G + li];
        float4 v3 = h4[(size_t)s3 * G + li];
        acc.x = fmaf(w0, v0.x, fmaf(w1, v1.x, fmaf(w2, v2.x, fmaf(w3, v3.x, acc.x))));
        acc.y = fmaf(w0, v0.y, fmaf(w1, v1.y, fmaf(w2, v2.y, fmaf(w3, v3.y, acc.y))));
        acc.z = fmaf(w0, v0.z, fmaf(w1, v1.z, fmaf(w2, v2.z, fmaf(w3, v3.z, acc.z))));
        acc.w = fmaf(w0, v0.w, fmaf(w1, v1.w, fmaf(w2, v2.w, fmaf(w3, v3.w, acc.w))));
    }
    for (; j < end; ++j) {
        int s = esrc[j];
        float w = ewt[j];
        float4 v = h4[(size_t)s * G + li];
        acc.x = fmaf(w, v.x, acc.x);
        acc.y = fmaf(w, v.y, acc.y);
        acc.z = fmaf(w, v.z, acc.z);
        acc.w = fmaf(w, v.w, acc.w);
    }

    out4[(size_t)node * G + li] = acc;
}

// ---------------------------------------------------------------------------
// Decode: hidden = z[s]*z[t]; logits = sum(hidden); hidden_n = hidden/||hidden||
// ---------------------------------------------------------------------------
__global__ void __launch_bounds__(256)
decode_kernel(const float* __restrict__ z, const int* __restrict__ eli,
              float* __restrict__ outh, float* __restrict__ outl, int EL)
{
    int tid = blockIdx.x * blockDim.x + threadIdx.x;
    int eid = tid >> 4;       // 16 lanes per edge
    int li  = tid & 15;
    int lane = threadIdx.x & 31;
    unsigned mask = 0xFFFFu << (lane & 16);   // group-local mask

    if (eid >= EL) return;

    int s = eli[eid];
    int t = eli[EL + eid];
    const float4* z4 = reinterpret_cast<const float4*>(z);
    float4 a = z4[(size_t)s * 16 + li];
    float4 b = z4[(size_t)t * 16 + li];

    float4 hh;
    hh.x = a.x * b.x; hh.y = a.y * b.y; hh.z = a.z * b.z; hh.w = a.w * b.w;

    float sum = hh.x + hh.y + hh.z + hh.w;
    float sq  = hh.x * hh.x + hh.y * hh.y + hh.z * hh.z + hh.w * hh.w;

    #pragma unroll
    for (int off = 8; off > 0; off >>= 1) {
        sum += __shfl_xor_sync(mask, sum, off);
        sq  += __shfl_xor_sync(mask, sq,  off);
    }

    float nrm = sqrtf(sq);
    float inv = 1.0f / fmaxf(nrm, 1e-12f);
    float4 o;
    o.x = hh.x * inv; o.y = hh.y * inv; o.z = hh.z * inv; o.w = hh.w * inv;
    reinterpret_cast<float4*>(outh)[(size_t)eid * 16 + li] = o;
    if (li == 0) outl[eid] = sum;
}

// ---------------------------------------------------------------------------
// Launch
// ---------------------------------------------------------------------------
extern "C" void kernel_launch(void* const* d_in, const int* in_sizes, int n_in,
                              void* d_out, int out_size)
{
    const float* x   = (const float*)d_in[0];
    const float* W1  = (const float*)d_in[1];
    const float* b1  = (const float*)d_in[2];
    const float* W2  = (const float*)d_in[3];
    const float* b2  = (const float*)d_in[4];
    const float* W3  = (const float*)d_in[5];
    const float* b3  = (const float*)d_in[6];
    const int*   ei  = (const int*)d_in[7];
    const int*   eli = (const int*)d_in[8];

    const int n  = in_sizes[0] / 128;
    const int E  = in_sizes[7] / 2;
    const int EL = in_sizes[8] / 2;

    float* out = (float*)d_out;
    float* out_hidden = out;
    float* out_logits = out + (size_t)EL * 64;

    float *d_dis, *d_h, *d_bufA, *d_bufB, *d_ewt;
    int *d_cnt, *d_rowptr, *d_cursor, *d_bsums, *d_esrc;
    cudaGetSymbolAddress((void**)&d_dis,    g_dis);
    cudaGetSymbolAddress((void**)&d_cnt,    g_cnt);
    cudaGetSymbolAddress((void**)&d_rowptr, g_rowptr);
    cudaGetSymbolAddress((void**)&d_cursor, g_cursor);
    cudaGetSymbolAddress((void**)&d_bsums,  g_bsums);
    cudaGetSymbolAddress((void**)&d_esrc,   g_esrc);
    cudaGetSymbolAddress((void**)&d_ewt,    g_ewt);
    cudaGetSymbolAddress((void**)&d_h,      g_h);
    cudaGetSymbolAddress((void**)&d_bufA,   g_bufA);
    cudaGetSymbolAddress((void**)&d_bufB,   g_bufB);

    cudaFuncSetAttribute(gemm_kernel<128, false>, cudaFuncAttributeMaxDynamicSharedMemorySize, 98304);
    cudaFuncSetAttribute(gemm_kernel<128, true>,  cudaFuncAttributeMaxDynamicSharedMemorySize, 98304);
    cudaFuncSetAttribute(gemm_kernel<64,  true>,  cudaFuncAttributeMaxDynamicSharedMemorySize, 65536);

    const int* src = ei;
    const int* dst = ei + E;

    const int nb = (n + 255) / 256;       // scan blocks (391 for n=100000)

    // ---- CSR build (by dst) ----
    zero_cnt_kernel<<<nb, 256>>>(d_cnt, n);
    count_kernel<<<(E + 255) / 256, 256>>>(d_cnt, dst, E);
    dis_kernel<<<nb, 256>>>(d_cnt, d_dis, n);
    // reuse g_cursor as the per-element partial-scan buffer during the scan
    scan1_kernel<<<nb, 256>>>(d_cnt, d_cursor, d_bsums, n);
    scan2_kernel<<<1, 1024>>>(d_bsums, nb);
    scan3_kernel<<<nb, 256>>>(d_cursor, d_bsums, d_rowptr, d_cursor, n, E);
    fill_kernel<<<(E + 255) / 256, 256>>>(src, dst, d_dis, d_cursor, d_esrc, d_ewt, E);

    const int gemm_blocks = (n + 63) / 64;
    const int agg128_blocks = ((n * 32) + 255) / 256;
    const int agg64_blocks  = ((n * 16) + 255) / 256;

    // Layer 1
    gemm_kernel<128, false><<<gemm_blocks, 256, 98304>>>(x, W1, b1, d_dis, d_h, d_bufA, n);
    agg_kernel<128><<<agg128_blocks, 256>>>(d_rowptr, d_esrc, d_ewt, d_h, d_bufA, n);

    // Layer 2
    gemm_kernel<128, true><<<gemm_blocks, 256, 98304>>>(d_bufA, W2, b2, d_dis, d_h, d_bufB, n);
    agg_kernel<128><<<agg128_blocks, 256>>>(d_rowptr, d_esrc, d_ewt, d_h, d_bufB, n);

    // Layer 3 (DOUT=64)
    gemm_kernel<64, true><<<gemm_blocks, 256, 65536>>>(d_bufB, W3, b3, d_dis, d_h, d_bufA, n);
    agg_kernel<64><<<agg64_blocks, 256>>>(d_rowptr, d_esrc, d_ewt, d_h, d_bufA, n);

    // Decode
    decode_kernel<<<((EL * 16) + 255) / 256, 256>>>(d_bufA, eli, out_hidden, out_logits, EL);
}

// round 3
// speedup vs baseline: 2.4741x; 1.4950x over previous
#include <cuda_runtime.h>
#include <cstdio>

// Problem constants (from reference): N=100000, E=1.6M, EL=200000
#define NMAX 100000
#define EMAX 1600000
#define KDIM 128

// Scratch (static __device__ arrays — no allocation allowed)
__device__ float g_dis[NMAX];             // d^-1/2
__device__ int   g_cnt[NMAX];             // in-degree histogram (excl self-loop)
__device__ int   g_rowptr[NMAX + 1];      // CSR row pointers (by dst)
__device__ int   g_cursor[NMAX];          // fill cursors (also scan partials)
__device__ int   g_bsums[1024];           // scan block sums
__device__ int   g_esrc[EMAX];            // CSR: src node per slot
__device__ float g_ewt[EMAX];             // CSR: edge weight dis[s]*dis[d]
__device__ float g_h[NMAX * 128];         // pre-aggregation features h = in @ W
__device__ float g_bufA[NMAX * 128];      // layer outputs (ping)
__device__ float g_bufB[NMAX * 128];      // layer outputs (pong)

// ---------------------------------------------------------------------------
// CSR build: histogram -> (scan + dis) -> fill
// ---------------------------------------------------------------------------
__global__ void zero_cnt_kernel(int* __restrict__ cnt, int n) {
    int i = blockIdx.x * blockDim.x + threadIdx.x;
    if (i < n) cnt[i] = 0;
}

__global__ void count_kernel(int* __restrict__ cnt, const int* __restrict__ dst, int E) {
    int e = blockIdx.x * blockDim.x + threadIdx.x;
    if (e < E) atomicAdd(&cnt[dst[e]], 1);
}

// Exclusive scan step 1 (per-block) + dis = rsqrt(cnt+1) fused.
__global__ void scan1_kernel(const int* __restrict__ cnt, int* __restrict__ part,
                             int* __restrict__ sums, float* __restrict__ dis, int n) {
    __shared__ int sm[256];
    int t = threadIdx.x;
    int i = blockIdx.x * 256 + t;
    int v = (i < n) ? cnt[i] : 0;
    if (i < n) dis[i] = rsqrtf((float)(v + 1));   // +1 self-loop
    sm[t] = v;
    __syncthreads();
    #pragma unroll
    for (int off = 1; off < 256; off <<= 1) {
        int a = (t >= off) ? sm[t - off] : 0;
        __syncthreads();
        sm[t] += a;
        __syncthreads();
    }
    if (i < n) part[i] = sm[t] - v;          // exclusive within block
    if (t == 255) sums[blockIdx.x] = sm[255];
}

// Step 2: single-block scan of block totals (nb <= 1024).
__global__ void scan2_kernel(int* __restrict__ sums, int nb) {
    __shared__ int sm[1024];
    int t = threadIdx.x;
    int v = (t < nb) ? sums[t] : 0;
    sm[t] = v;
    __syncthreads();
    #pragma unroll
    for (int off = 1; off < 1024; off <<= 1) {
        int a = (t >= off) ? sm[t - off] : 0;
        __syncthreads();
        sm[t] += a;
        __syncthreads();
    }
    if (t < nb) sums[t] = sm[t] - v;          // exclusive block offsets
}

// Step 3: combine, write row_ptr + cursor.
__global__ void scan3_kernel(const int* __restrict__ part, const int* __restrict__ sums,
                             int* __restrict__ row_ptr, int* __restrict__ cursor,
                             int n, int E) {
    int i = blockIdx.x * blockDim.x + threadIdx.x;
    if (i < n) {
        int v = part[i] + sums[i >> 8];
        row_ptr[i] = v;
        cursor[i] = v;
    }
    if (i == 0) row_ptr[n] = E;
}

__global__ void fill_kernel(const int* __restrict__ src, const int* __restrict__ dst,
                            const float* __restrict__ dis,
                            int* __restrict__ cursor, int* __restrict__ esrc,
                            float* __restrict__ ewt, int E) {
    int e = blockIdx.x * blockDim.x + threadIdx.x;
    if (e >= E) return;
    int s = src[e];
    int d = dst[e];
    int pos = atomicAdd(&cursor[d], 1);
    esrc[pos] = s;
    ewt[pos] = dis[s] * dis[d];
}

// ---------------------------------------------------------------------------
// GEMM: h = relu?(in) @ W
// 64-row tile, full K=128 staged; each thread computes 4 rows x 8 cols
// (cols c2 and c2+DOUT/2 as two float4 groups). sX pitched to 132 words to
// avoid bank conflicts on scalar x broadcasts.
// ---------------------------------------------------------------------------
template <int DOUT, bool RELU_IN>
__global__ void __launch_bounds__(256)
gemm_kernel(const float* __restrict__ in, const float* __restrict__ W,
            float* __restrict__ h, int n)
{
    constexpr int ROWS = 64;
    constexpr int THREADS = 256;
    constexpr int CG2  = DOUT / 8;          // threads across columns
    constexpr int RSUB = THREADS / CG2;     // row sub-partitions
    constexpr int RPT  = ROWS / RSUB;       // rows per thread
    constexpr int WP4  = DOUT / 4;          // float4 per W row
    constexpr int XP4  = KDIM / 4 + 1;      // padded pitch (33 float4 = 132 words)

    extern __shared__ float smem[];
    float*  sW  = smem;                      // [KDIM * DOUT]
    float4* sW4 = reinterpret_cast<float4*>(sW);
    float*  sX  = smem + KDIM * DOUT;        // [ROWS * XP4 * 4]
    float4* sX4 = reinterpret_cast<float4*>(sX);

    const int t = threadIdx.x;
    const int row0 = blockIdx.x * ROWS;

    // Stage W
    const float4* W4 = reinterpret_cast<const float4*>(W);
    #pragma unroll
    for (int i = t; i < KDIM * DOUT / 4; i += THREADS) sW4[i] = W4[i];

    // Stage X tile (ReLU folded into the load), padded pitch
    const float4* in4 = reinterpret_cast<const float4*>(in);
    #pragma unroll
    for (int i = t; i < ROWS * (KDIM / 4); i += THREADS) {
        int r = i / (KDIM / 4);
        int c = i % (KDIM / 4);
        int gr = row0 + r;
        float4 v = make_float4(0.f, 0.f, 0.f, 0.f);
        if (gr < n) v = in4[(size_t)gr * (KDIM / 4) + c];
        if (RELU_IN) {
            v.x = fmaxf(v.x, 0.f); v.y = fmaxf(v.y, 0.f);
            v.z = fmaxf(v.z, 0.f); v.w = fmaxf(v.w, 0.f);
        }
        sX4[r * XP4 + c] = v;
    }
    __syncthreads();

    const int c2 = t % CG2;
    const int rs = t / CG2;

    float4 acc0[RPT], acc1[RPT];
    #pragma unroll
    for (int j = 0; j < RPT; ++j) {
        acc0[j] = make_float4(0.f, 0.f, 0.f, 0.f);
        acc1[j] = make_float4(0.f, 0.f, 0.f, 0.f);
    }

    #pragma unroll 8
    for (int k = 0; k < KDIM; ++k) {
        float4 w0 = sW4[k * WP4 + c2];
        float4 w1 = sW4[k * WP4 + c2 + CG2];
        #pragma unroll
        for (int j = 0; j < RPT; ++j) {
            float xv = sX[(rs + j * RSUB) * (XP4 * 4) + k];
            acc0[j].x = fmaf(xv, w0.x, acc0[j].x);
            acc0[j].y = fmaf(xv, w0.y, acc0[j].y);
            acc0[j].z = fmaf(xv, w0.z, acc0[j].z);
            acc0[j].w = fmaf(xv, w0.w, acc0[j].w);
            acc1[j].x = fmaf(xv, w1.x, acc1[j].x);
            acc1[j].y = fmaf(xv, w1.y, acc1[j].y);
            acc1[j].z = fmaf(xv, w1.z, acc1[j].z);
            acc1[j].w = fmaf(xv, w1.w, acc1[j].w);
        }
    }

    float4* h4 = reinterpret_cast<float4*>(h);
    #pragma unroll
    for (int j = 0; j < RPT; ++j) {
        int gr = row0 + rs + j * RSUB;
        if (gr < n) {
            h4[(size_t)gr * WP4 + c2]       = acc0[j];
            h4[(size_t)gr * WP4 + c2 + CG2] = acc1[j];
        }
    }
}

// ---------------------------------------------------------------------------
// CSR gather-aggregate with fused self-loop + bias:
// out[v] = dis[v]^2 * h[v] + b + sum_{e in in(v)} ewt[e] * h[esrc[e]]
// ---------------------------------------------------------------------------
template <int D>
__global__ void __launch_bounds__(256)
agg_kernel(const int* __restrict__ rp, const int* __restrict__ esrc,
           const float* __restrict__ ewt, const float* __restrict__ h,
           const float* __restrict__ dis, const float* __restrict__ bias,
           float* __restrict__ out, int n)
{
    constexpr int G = D / 4;
    int tid = blockIdx.x * blockDim.x + threadIdx.x;
    int node = tid / G;
    int li   = tid % G;
    if (node >= n) return;

    int beg = rp[node];
    int end = rp[node + 1];

    const float4* h4 = reinterpret_cast<const float4*>(h);

    // self-loop + bias
    float d = dis[node];
    float dd = d * d;
    float4 hv = h4[(size_t)node * G + li];
    float4 b4 = reinterpret_cast<const float4*>(bias)[li];
    float4 acc;
    acc.x = fmaf(dd, hv.x, b4.x);
    acc.y = fmaf(dd, hv.y, b4.y);
    acc.z = fmaf(dd, hv.z, b4.z);
    acc.w = fmaf(dd, hv.w, b4.w);

    int j = beg;
    for (; j + 4 <= end; j += 4) {
        int s0 = esrc[j], s1 = esrc[j + 1], s2 = esrc[j + 2], s3 = esrc[j + 3];
        float w0 = ewt[j], w1 = ewt[j + 1], w2 = ewt[j + 2], w3 = ewt[j + 3];
        float4 v0 = h4[(size_t)s0 * G + li];
        float4 v1 = h4[(size_t)s1 * G + li];
        float4 v2 = h4[(size_t)s2 * G + li];
        float4 v3 = h4[(size_t)s3 * G + li];
        acc.x = fmaf(w0, v0.x, fmaf(w1, v1.x, fmaf(w2, v2.x, fmaf(w3, v3.x, acc.x))));
        acc.y = fmaf(w0, v0.y, fmaf(w1, v1.y, fmaf(w2, v2.y, fmaf(w3, v3.y, acc.y))));
        acc.z = fmaf(w0, v0.z, fmaf(w1, v1.z, fmaf(w2, v2.z, fmaf(w3, v3.z, acc.z))));
        acc.w = fmaf(w0, v0.w, fmaf(w1, v1.w, fmaf(w2, v2.w, fmaf(w3, v3.w, acc.w))));
    }
    for (; j < end; ++j) {
        int s = esrc[j];
        float w = ewt[j];
        float4 v = h4[(size_t)s * G + li];
        acc.x = fmaf(w, v.x, acc.x);
        acc.y = fmaf(w, v.y, acc.y);
        acc.z = fmaf(w, v.z, acc.z);
        acc.w = fmaf(w, v.w, acc.w);
    }

    reinterpret_cast<float4*>(out)[(size_t)node * G + li] = acc;
}

// ---------------------------------------------------------------------------
// Decode: hidden = z[s]*z[t]; logits = sum(hidden); hidden_n = hidden/||hidden||
// ---------------------------------------------------------------------------
__global__ void __launch_bounds__(256)
decode_kernel(const float* __restrict__ z, const int* __restrict__ eli,
              float* __restrict__ outh, float* __restrict__ outl, int EL)
{
    int tid = blockIdx.x * blockDim.x + threadIdx.x;
    int eid = tid >> 4;       // 16 lanes per edge
    int li  = tid & 15;
    int lane = threadIdx.x & 31;
    unsigned mask = 0xFFFFu << (lane & 16);   // group-local mask

    if (eid >= EL) return;

    int s = eli[eid];
    int t = eli[EL + eid];
    const float4* z4 = reinterpret_cast<const float4*>(z);
    float4 a = z4[(size_t)s * 16 + li];
    float4 b = z4[(size_t)t * 16 + li];

    float4 hh;
    hh.x = a.x * b.x; hh.y = a.y * b.y; hh.z = a.z * b.z; hh.w = a.w * b.w;

    float sum = hh.x + hh.y + hh.z + hh.w;
    float sq  = hh.x * hh.x + hh.y * hh.y + hh.z * hh.z + hh.w * hh.w;

    #pragma unroll
    for (int off = 8; off > 0; off >>= 1) {
        sum += __shfl_xor_sync(mask, sum, off);
        sq  += __shfl_xor_sync(mask, sq,  off);
    }

    float nrm = sqrtf(sq);
    float inv = 1.0f / fmaxf(nrm, 1e-12f);
    float4 o;
    o.x = hh.x * inv; o.y = hh.y * inv; o.z = hh.z * inv; o.w = hh.w * inv;
    reinterpret_cast<float4*>(outh)[(size_t)eid * 16 + li] = o;
    if (li == 0) outl[eid] = sum;
}

// ---------------------------------------------------------------------------
// Launch
// ---------------------------------------------------------------------------
extern "C" void kernel_launch(void* const* d_in, const int* in_sizes, int n_in,
                              void* d_out, int out_size)
{
    const float* x   = (const float*)d_in[0];
    const float* W1  = (const float*)d_in[1];
    const float* b1  = (const float*)d_in[2];
    const float* W2  = (const float*)d_in[3];
    const float* b2  = (const float*)d_in[4];
    const float* W3  = (const float*)d_in[5];
    const float* b3  = (const float*)d_in[6];
    const int*   ei  = (const int*)d_in[7];
    const int*   eli = (const int*)d_in[8];

    const int n  = in_sizes[0] / 128;
    const int E  = in_sizes[7] / 2;
    const int EL = in_sizes[8] / 2;

    float* out = (float*)d_out;
    float* out_hidden = out;
    float* out_logits = out + (size_t)EL * 64;

    float *d_dis, *d_h, *d_bufA, *d_bufB, *d_ewt;
    int *d_cnt, *d_rowptr, *d_cursor, *d_bsums, *d_esrc;
    cudaGetSymbolAddress((void**)&d_dis,    g_dis);
    cudaGetSymbolAddress((void**)&d_cnt,    g_cnt);
    cudaGetSymbolAddress((void**)&d_rowptr, g_rowptr);
    cudaGetSymbolAddress((void**)&d_cursor, g_cursor);
    cudaGetSymbolAddress((void**)&d_bsums,  g_bsums);
    cudaGetSymbolAddress((void**)&d_esrc,   g_esrc);
    cudaGetSymbolAddress((void**)&d_ewt,    g_ewt);
    cudaGetSymbolAddress((void**)&d_h,      g_h);
    cudaGetSymbolAddress((void**)&d_bufA,   g_bufA);
    cudaGetSymbolAddress((void**)&d_bufB,   g_bufB);

    constexpr int SMEM128 = (128 * 128 + 64 * 132) * 4;   // 99328
    constexpr int SMEM64  = (128 * 64 + 64 * 132) * 4;    // 66560
    cudaFuncSetAttribute(gemm_kernel<128, false>, cudaFuncAttributeMaxDynamicSharedMemorySize, SMEM128);
    cudaFuncSetAttribute(gemm_kernel<128, true>,  cudaFuncAttributeMaxDynamicSharedMemorySize, SMEM128);
    cudaFuncSetAttribute(gemm_kernel<64,  true>,  cudaFuncAttributeMaxDynamicSharedMemorySize, SMEM64);

    const int* src = ei;
    const int* dst = ei + E;

    const int nb = (n + 255) / 256;       // scan blocks (391 for n=100000)
    const int gemm_blocks = (n + 63) / 64;
    const int agg128_blocks = ((n * 32) + 255) / 256;
    const int agg64_blocks  = ((n * 16) + 255) / 256;

    // ---- CSR build; gemm1 placed at launch index 5 for the ncu window ----
    zero_cnt_kernel<<<nb, 256>>>(d_cnt, n);                                     // 0
    count_kernel<<<(E + 255) / 256, 256>>>(d_cnt, dst, E);                      // 1
    scan1_kernel<<<nb, 256>>>(d_cnt, d_cursor, d_bsums, d_dis, n);              // 2
    scan2_kernel<<<1, 1024>>>(d_bsums, nb);                                     // 3
    scan3_kernel<<<nb, 256>>>(d_cursor, d_bsums, d_rowptr, d_cursor, n, E);     // 4

    // Layer 1 GEMM (profiled launch)
    gemm_kernel<128, false><<<gemm_blocks, 256, SMEM128>>>(x, W1, d_h, n);      // 5

    // CSR fill (independent of gemm1; needs dis from scan1)
    fill_kernel<<<(E + 255) / 256, 256>>>(src, dst, d_dis, d_cursor, d_esrc, d_ewt, E); // 6

    // Layer 1 aggregate
    agg_kernel<128><<<agg128_blocks, 256>>>(d_rowptr, d_esrc, d_ewt, d_h, d_dis, b1, d_bufA, n);

    // Layer 2
    gemm_kernel<128, true><<<gemm_blocks, 256, SMEM128>>>(d_bufA, W2, d_h, n);
    agg_kernel<128><<<agg128_blocks, 256>>>(d_rowptr, d_esrc, d_ewt, d_h, d_dis, b2, d_bufB, n);

    // Layer 3 (DOUT=64)
    gemm_kernel<64, true><<<gemm_blocks, 256, SMEM64>>>(d_bufB, W3, d_h, n);
    agg_kernel<64><<<agg64_blocks, 256>>>(d_rowptr, d_esrc, d_ewt, d_h, d_dis, b3, d_bufA, n);

    // Decode
    decode_kernel<<<((EL * 16) + 255) / 256, 256>>>(d_bufA, eli, out_hidden, out_logits, EL);
}

// round 6
// speedup vs baseline: 3.2224x; 1.3024x over previous
#include <cuda_runtime.h>
#include <cuda_bf16.h>
#include <cstdio>
#include <cstdint>

// Problem constants: N=100000, E=1.6M, EL=200000
#define NMAX 100000
#define EMAX 1600000

// Scratch (static __device__ arrays — no allocation allowed)
__device__ float g_dis[NMAX];
__device__ int   g_cnt[NMAX];
__device__ int   g_rowptr[NMAX + 1];
__device__ int   g_cursor[NMAX];
__device__ int   g_bsums[1024];
__device__ int   g_esrc[EMAX];
__device__ float g_ewt[EMAX];
__device__ float g_h[NMAX * 128];
__device__ float g_bufA[NMAX * 128];
__device__ float g_bufB[NMAX * 128];
// Transposed bf16 hi/lo weights: Wt[n][k] = W[k][n]
__device__ __nv_bfloat16 g_w1h[128 * 128], g_w1l[128 * 128];
__device__ __nv_bfloat16 g_w2h[128 * 128], g_w2l[128 * 128];
__device__ __nv_bfloat16 g_w3h[64 * 128],  g_w3l[64 * 128];

// ---------------------------------------------------------------------------
// PTX helpers (baseline sm_80+ features only — no tcgen05 in this harness)
// ---------------------------------------------------------------------------
__device__ __forceinline__ uint32_t smem_u32(const void* p) {
    uint32_t a;
    asm("{ .reg .u64 t; cvta.to.shared.u64 t, %1; cvt.u32.u64 %0, t; }" : "=r"(a) : "l"(p));
    return a;
}
__device__ __forceinline__ void ldsm_x4(uint32_t* r, uint32_t addr) {
    asm volatile("ldmatrix.sync.aligned.m8n8.x4.shared.b16 {%0,%1,%2,%3}, [%4];"
                 : "=r"(r[0]), "=r"(r[1]), "=r"(r[2]), "=r"(r[3]) : "r"(addr));
}
__device__ __forceinline__ void mma16816(float* d, const uint32_t* a, uint32_t b0, uint32_t b1) {
    asm volatile("mma.sync.aligned.m16n8k16.row.col.f32.bf16.bf16.f32 "
                 "{%0,%1,%2,%3}, {%4,%5,%6,%7}, {%8,%9}, {%0,%1,%2,%3};"
                 : "+f"(d[0]), "+f"(d[1]), "+f"(d[2]), "+f"(d[3])
                 : "r"(a[0]), "r"(a[1]), "r"(a[2]), "r"(a[3]), "r"(b0), "r"(b1));
}
__device__ __forceinline__ uint32_t pack_bf2(float x, float y) {
    __nv_bfloat162 v;
    v.x = __float2bfloat16(x);
    v.y = __float2bfloat16(y);
    return *reinterpret_cast<uint32_t*>(&v);
}

// ---------------------------------------------------------------------------
// Weight prep: Wt_hi/lo[n*128+k] = bf16split(W[k*DOUT+n])
// ---------------------------------------------------------------------------
__global__ void prep_w_kernel(const float* __restrict__ W1, const float* __restrict__ W2,
                              const float* __restrict__ W3,
                              __nv_bfloat16* __restrict__ w1h, __nv_bfloat16* __restrict__ w1l,
                              __nv_bfloat16* __restrict__ w2h, __nv_bfloat16* __restrict__ w2l,
                              __nv_bfloat16* __restrict__ w3h, __nv_bfloat16* __restrict__ w3l)
{
    int i = blockIdx.x * blockDim.x + threadIdx.x;
    const float* W; __nv_bfloat16 *oh, *ol; int dout, j;
    if (i < 16384)      { W = W1; oh = w1h; ol = w1l; dout = 128; j = i; }
    else if (i < 32768) { W = W2; oh = w2h; ol = w2l; dout = 128; j = i - 16384; }
    else if (i < 40960) { W = W3; oh = w3h; ol = w3l; dout = 64;  j = i - 32768; }
    else return;
    int nn = j >> 7, k = j & 127;
    float w = W[k * dout + nn];
    __nv_bfloat16 hi = __float2bfloat16(w);
    float lo = w - __bfloat162float(hi);
    oh[j] = hi;
    ol[j] = __float2bfloat16(lo);
}

// ---------------------------------------------------------------------------
// mma.sync bf16-split GEMM: h = relu?(in) @ W
// Block: 512 thr, 128 rows x DOUT cols, K=128. Warp grid 4x4, warp tile
// 32 x (DOUT/4). 3 products: Ah*Bh + Ah*Bl + Al*Bh (fp32 accum).
// smem pitch 136 halfwords (272B) -> conflict-free ldmatrix.
// ---------------------------------------------------------------------------
template <int DOUT, bool RELU_IN>
__global__ void __launch_bounds__(512)
gemm_mma_kernel(const float* __restrict__ in, const __nv_bfloat16* __restrict__ wtHi,
                const __nv_bfloat16* __restrict__ wtLo, float* __restrict__ h, int n)
{
    constexpr int THREADS = 512;
    constexpr int ROWS = 128;
    constexpr int K = 128;
    constexpr int PITCH = 136;                   // halfwords per smem row
    constexpr int TN = DOUT / 4;                 // warp tile cols (32 or 16)
    constexpr int NT = TN / 8;                   // n-tiles per warp (4 or 2)
    constexpr int NG = NT / 2;                   // ldmatrix.x4 groups for B (2 or 1)
    // smem halfword offsets
    constexpr int A_HI = 0;
    constexpr int A_LO = ROWS * PITCH;           // 17408
    constexpr int B_HI = 2 * ROWS * PITCH;       // 34816
    constexpr int B_LO = B_HI + DOUT * PITCH;

    extern __shared__ __nv_bfloat16 smem[];
    const int t = threadIdx.x;
    const int row0 = blockIdx.x * ROWS;

    // ---- Stage A (fp32 -> hi/lo bf16, ReLU folded) ----
    const float4* in4 = reinterpret_cast<const float4*>(in);
    #pragma unroll
    for (int i = t; i < ROWS * (K / 4); i += THREADS) {
        int r = i >> 5, c4 = i & 31;
        int gr = row0 + r;
        float4 v = make_float4(0.f, 0.f, 0.f, 0.f);
        if (gr < n) v = in4[(size_t)gr * (K / 4) + c4];
        if (RELU_IN) {
            v.x = fmaxf(v.x, 0.f); v.y = fmaxf(v.y, 0.f);
            v.z = fmaxf(v.z, 0.f); v.w = fmaxf(v.w, 0.f);
        }
        uint32_t h0 = pack_bf2(v.x, v.y);
        uint32_t h1 = pack_bf2(v.z, v.w);
        __nv_bfloat162 hh0 = *reinterpret_cast<__nv_bfloat162*>(&h0);
        __nv_bfloat162 hh1 = *reinterpret_cast<__nv_bfloat162*>(&h1);
        uint32_t l0 = pack_bf2(v.x - __bfloat162float(hh0.x), v.y - __bfloat162float(hh0.y));
        uint32_t l1 = pack_bf2(v.z - __bfloat162float(hh1.x), v.w - __bfloat162float(hh1.y));
        int off = r * PITCH + c4 * 4;
        *reinterpret_cast<uint2*>(smem + A_HI + off) = make_uint2(h0, h1);
        *reinterpret_cast<uint2*>(smem + A_LO + off) = make_uint2(l0, l1);
    }

    // ---- Stage B (transposed bf16 weights, coalesced 16B chunks) ----
    const uint4* wh4 = reinterpret_cast<const uint4*>(wtHi);
    const uint4* wl4 = reinterpret_cast<const uint4*>(wtLo);
    #pragma unroll
    for (int i = t; i < DOUT * 16; i += THREADS) {
        int nn = i >> 4, j = i & 15;
        int off = nn * PITCH + j * 8;
        *reinterpret_cast<uint4*>(smem + B_HI + off) = wh4[i];
        *reinterpret_cast<uint4*>(smem + B_LO + off) = wl4[i];
    }
    __syncthreads();

    // ---- Fragment addresses ----
    const int wid  = t >> 5;
    const int lane = t & 31;
    const int warpM = wid >> 2;   // 0..3
    const int warpN = wid & 3;    // 0..3

    // A ldmatrix.x4: lane -> row (lane%16), k-col (lane/16)*8
    const int aRow = warpM * 32 + (lane & 15);
    const int aCol = (lane >> 4) * 8;
    const uint32_t sb = smem_u32(smem);
    const uint32_t aHiAddr = sb + (uint32_t)(A_HI + aRow * PITCH + aCol) * 2;
    const uint32_t aLoAddr = aHiAddr + (uint32_t)(A_LO - A_HI) * 2;
    // B ldmatrix.x4: covers 2 n-tiles; lane -> n = base + ((lane&16)>>1) + (lane&7),
    // k-col = (lane&8)
    const int bN = warpN * TN + ((lane & 16) >> 1) + (lane & 7);
    const int bK = lane & 8;
    const uint32_t bHiAddr = sb + (uint32_t)(B_HI + bN * PITCH + bK) * 2;
    const uint32_t bLoAddr = bHiAddr + (uint32_t)(DOUT * PITCH) * 2;

    float acc[2][NT][4];
    #pragma unroll
    for (int mt = 0; mt < 2; ++mt)
        #pragma unroll
        for (int nt = 0; nt < NT; ++nt)
            #pragma unroll
            for (int r = 0; r < 4; ++r) acc[mt][nt][r] = 0.f;

    #pragma unroll
    for (int kt = 0; kt < 8; ++kt) {
        const uint32_t ka = kt * 32;          // 16 halfwords = 32 bytes per k-tile
        uint32_t ah[2][4], al[2][4], bh[NG][4], bl[NG][4];
        ldsm_x4(ah[0], aHiAddr + ka);
        ldsm_x4(ah[1], aHiAddr + ka + 16 * PITCH * 2);
        #pragma unroll
        for (int g = 0; g < NG; ++g)
            ldsm_x4(bh[g], bHiAddr + ka + g * 16 * PITCH * 2);

        // hi * hi
        #pragma unroll
        for (int mt = 0; mt < 2; ++mt)
            #pragma unroll
            for (int g = 0; g < NG; ++g) {
                mma16816(acc[mt][2 * g + 0], ah[mt], bh[g][0], bh[g][1]);
                mma16816(acc[mt][2 * g + 1], ah[mt], bh[g][2], bh[g][3]);
            }

        // hi * lo
        #pragma unroll
        for (int g = 0; g < NG; ++g)
            ldsm_x4(bl[g], bLoAddr + ka + g * 16 * PITCH * 2);
        #pragma unroll
        for (int mt = 0; mt < 2; ++mt)
            #pragma unroll
            for (int g = 0; g < NG; ++g) {
                mma16816(acc[mt][2 * g + 0], ah[mt], bl[g][0], bl[g][1]);
                mma16816(acc[mt][2 * g + 1], ah[mt], bl[g][2], bl[g][3]);
            }

        // lo * hi
        ldsm_x4(al[0], aLoAddr + ka);
        ldsm_x4(al[1], aLoAddr + ka + 16 * PITCH * 2);
        #pragma unroll
        for (int mt = 0; mt < 2; ++mt)
            #pragma unroll
            for (int g = 0; g < NG; ++g) {
                mma16816(acc[mt][2 * g + 0], al[mt], bh[g][0], bh[g][1]);
                mma16816(acc[mt][2 * g + 1], al[mt], bh[g][2], bh[g][3]);
            }
    }

    // ---- Epilogue: direct float2 stores from fragments ----
    float2* h2 = reinterpret_cast<float2*>(h);
    #pragma unroll
    for (int mt = 0; mt < 2; ++mt) {
        #pragma unroll
        for (int nt = 0; nt < NT; ++nt) {
            int r = row0 + warpM * 32 + mt * 16 + (lane >> 2);
            int c = warpN * TN + nt * 8 + 2 * (lane & 3);
            if (r < n)
                h2[(size_t)r * (DOUT / 2) + c / 2] = make_float2(acc[mt][nt][0], acc[mt][nt][1]);
            if (r + 8 < n)
                h2[(size_t)(r + 8) * (DOUT / 2) + c / 2] = make_float2(acc[mt][nt][2], acc[mt][nt][3]);
        }
    }
}

// ---------------------------------------------------------------------------
// CSR build kernels
// ---------------------------------------------------------------------------
__global__ void zero_cnt_kernel(int* __restrict__ cnt, int n) {
    int i = blockIdx.x * blockDim.x + threadIdx.x;
    if (i < n) cnt[i] = 0;
}

__global__ void count_kernel(int* __restrict__ cnt, const int* __restrict__ dst, int E) {
    int e = blockIdx.x * blockDim.x + threadIdx.x;
    if (e < E) atomicAdd(&cnt[dst[e]], 1);
}

__global__ void scan1_kernel(const int* __restrict__ cnt, int* __restrict__ part,
                             int* __restrict__ sums, float* __restrict__ dis, int n) {
    __shared__ int sm[256];
    int t = threadIdx.x;
    int i = blockIdx.x * 256 + t;
    int v = (i < n) ? cnt[i] : 0;
    if (i < n) dis[i] = rsqrtf((float)(v + 1));
    sm[t] = v;
    __syncthreads();
    #pragma unroll
    for (int off = 1; off < 256; off <<= 1) {
        int a = (t >= off) ? sm[t - off] : 0;
        __syncthreads();
        sm[t] += a;
        __syncthreads();
    }
    if (i < n) part[i] = sm[t] - v;
    if (t == 255) sums[blockIdx.x] = sm[255];
}

__global__ void scan2_kernel(int* __restrict__ sums, int nb) {
    __shared__ int sm[1024];
    int t = threadIdx.x;
    int v = (t < nb) ? sums[t] : 0;
    sm[t] = v;
    __syncthreads();
    #pragma unroll
    for (int off = 1; off < 1024; off <<= 1) {
        int a = (t >= off) ? sm[t - off] : 0;
        __syncthreads();
        sm[t] += a;
        __syncthreads();
    }
    if (t < nb) sums[t] = sm[t] - v;
}

__global__ void scan3_kernel(const int* __restrict__ part, const int* __restrict__ sums,
                             int* __restrict__ row_ptr, int* __restrict__ cursor,
                             int n, int E) {
    int i = blockIdx.x * blockDim.x + threadIdx.x;
    if (i < n) {
        int v = part[i] + sums[i >> 8];
        row_ptr[i] = v;
        cursor[i] = v;
    }
    if (i == 0) row_ptr[n] = E;
}

__global__ void fill_kernel(const int* __restrict__ src, const int* __restrict__ dst,
                            const float* __restrict__ dis,
                            int* __restrict__ cursor, int* __restrict__ esrc,
                            float* __restrict__ ewt, int E) {
    int e = blockIdx.x * blockDim.x + threadIdx.x;
    if (e >= E) return;
    int s = src[e];
    int d = dst[e];
    int pos = atomicAdd(&cursor[d], 1);
    esrc[pos] = s;
    ewt[pos] = dis[s] * dis[d];
}

// ---------------------------------------------------------------------------
// CSR gather-aggregate with fused self-loop + bias
// ---------------------------------------------------------------------------
template <int D>
__global__ void __launch_bounds__(256)
agg_kernel(const int* __restrict__ rp, const int* __restrict__ esrc,
           const float* __restrict__ ewt, const float* __restrict__ h,
           const float* __restrict__ dis, const float* __restrict__ bias,
           float* __restrict__ out, int n)
{
    constexpr int G = D / 4;
    int tid = blockIdx.x * blockDim.x + threadIdx.x;
    int node = tid / G;
    int li   = tid % G;
    if (node >= n) return;

    int beg = rp[node];
    int end = rp[node + 1];

    const float4* h4 = reinterpret_cast<const float4*>(h);

    float d = dis[node];
    float dd = d * d;
    float4 hv = h4[(size_t)node * G + li];
    float4 b4 = reinterpret_cast<const float4*>(bias)[li];
    float4 acc;
    acc.x = fmaf(dd, hv.x, b4.x);
    acc.y = fmaf(dd, hv.y, b4.y);
    acc.z = fmaf(dd, hv.z, b4.z);
    acc.w = fmaf(dd, hv.w, b4.w);

    int j = beg;
    for (; j + 4 <= end; j += 4) {
        int s0 = esrc[j], s1 = esrc[j + 1], s2 = esrc[j + 2], s3 = esrc[j + 3];
        float w0 = ewt[j], w1 = ewt[j + 1], w2 = ewt[j + 2], w3 = ewt[j + 3];
        float4 v0 = h4[(size_t)s0 * G + li];
        float4 v1 = h4[(size_t)s1 * G + li];
        float4 v2 = h4[(size_t)s2 * G + li];
        float4 v3 = h4[(size_t)s3 * G + li];
        acc.x = fmaf(w0, v0.x, fmaf(w1, v1.x, fmaf(w2, v2.x, fmaf(w3, v3.x, acc.x))));
        acc.y = fmaf(w0, v0.y, fmaf(w1, v1.y, fmaf(w2, v2.y, fmaf(w3, v3.y, acc.y))));
        acc.z = fmaf(w0, v0.z, fmaf(w1, v1.z, fmaf(w2, v2.z, fmaf(w3, v3.z, acc.z))));
        acc.w = fmaf(w0, v0.w, fmaf(w1, v1.w, fmaf(w2, v2.w, fmaf(w3, v3.w, acc.w))));
    }
    for (; j < end; ++j) {
        int s = esrc[j];
        float w = ewt[j];
        float4 v = h4[(size_t)s * G + li];
        acc.x = fmaf(w, v.x, acc.x);
        acc.y = fmaf(w, v.y, acc.y);
        acc.z = fmaf(w, v.z, acc.z);
        acc.w = fmaf(w, v.w, acc.w);
    }

    reinterpret_cast<float4*>(out)[(size_t)node * G + li] = acc;
}

// ---------------------------------------------------------------------------
// Decode
// ---------------------------------------------------------------------------
__global__ void __launch_bounds__(256)
decode_kernel(const float* __restrict__ z, const int* __restrict__ eli,
              float* __restrict__ outh, float* __restrict__ outl, int EL)
{
    int tid = blockIdx.x * blockDim.x + threadIdx.x;
    int eid = tid >> 4;
    int li  = tid & 15;
    int lane = threadIdx.x & 31;
    unsigned mask = 0xFFFFu << (lane & 16);

    if (eid >= EL) return;

    int s = eli[eid];
    int t = eli[EL + eid];
    const float4* z4 = reinterpret_cast<const float4*>(z);
    float4 a = z4[(size_t)s * 16 + li];
    float4 b = z4[(size_t)t * 16 + li];

    float4 hh;
    hh.x = a.x * b.x; hh.y = a.y * b.y; hh.z = a.z * b.z; hh.w = a.w * b.w;

    float sum = hh.x + hh.y + hh.z + hh.w;
    float sq  = hh.x * hh.x + hh.y * hh.y + hh.z * hh.z + hh.w * hh.w;

    #pragma unroll
    for (int off = 8; off > 0; off >>= 1) {
        sum += __shfl_xor_sync(mask, sum, off);
        sq  += __shfl_xor_sync(mask, sq,  off);
    }

    float nrm = sqrtf(sq);
    float inv = 1.0f / fmaxf(nrm, 1e-12f);
    float4 o;
    o.x = hh.x * inv; o.y = hh.y * inv; o.z = hh.z * inv; o.w = hh.w * inv;
    reinterpret_cast<float4*>(outh)[(size_t)eid * 16 + li] = o;
    if (li == 0) outl[eid] = sum;
}

// ---------------------------------------------------------------------------
// Launch
// ---------------------------------------------------------------------------
extern "C" void kernel_launch(void* const* d_in, const int* in_sizes, int n_in,
                              void* d_out, int out_size)
{
    const float* x   = (const float*)d_in[0];
    const float* W1  = (const float*)d_in[1];
    const float* b1  = (const float*)d_in[2];
    const float* W2  = (const float*)d_in[3];
    const float* b2  = (const float*)d_in[4];
    const float* W3  = (const float*)d_in[5];
    const float* b3  = (const float*)d_in[6];
    const int*   ei  = (const int*)d_in[7];
    const int*   eli = (const int*)d_in[8];

    const int n  = in_sizes[0] / 128;
    const int E  = in_sizes[7] / 2;
    const int EL = in_sizes[8] / 2;

    float* out = (float*)d_out;
    float* out_hidden = out;
    float* out_logits = out + (size_t)EL * 64;

    float *d_dis, *d_h, *d_bufA, *d_bufB, *d_ewt;
    int *d_cnt, *d_rowptr, *d_cursor, *d_bsums, *d_esrc;
    __nv_bfloat16 *d_w1h, *d_w1l, *d_w2h, *d_w2l, *d_w3h, *d_w3l;
    cudaGetSymbolAddress((void**)&d_dis,    g_dis);
    cudaGetSymbolAddress((void**)&d_cnt,    g_cnt);
    cudaGetSymbolAddress((void**)&d_rowptr, g_rowptr);
    cudaGetSymbolAddress((void**)&d_cursor, g_cursor);
    cudaGetSymbolAddress((void**)&d_bsums,  g_bsums);
    cudaGetSymbolAddress((void**)&d_esrc,   g_esrc);
    cudaGetSymbolAddress((void**)&d_ewt,    g_ewt);
    cudaGetSymbolAddress((void**)&d_h,      g_h);
    cudaGetSymbolAddress((void**)&d_bufA,   g_bufA);
    cudaGetSymbolAddress((void**)&d_bufB,   g_bufB);
    cudaGetSymbolAddress((void**)&d_w1h,    g_w1h);
    cudaGetSymbolAddress((void**)&d_w1l,    g_w1l);
    cudaGetSymbolAddress((void**)&d_w2h,    g_w2h);
    cudaGetSymbolAddress((void**)&d_w2l,    g_w2l);
    cudaGetSymbolAddress((void**)&d_w3h,    g_w3h);
    cudaGetSymbolAddress((void**)&d_w3l,    g_w3l);

    // smem: A hi/lo (2*34816 B) + B hi/lo (2*DOUT*272 B)
    constexpr int SMEM128 = 2 * 128 * 136 * 2 + 2 * 128 * 136 * 2;  // 139264
    constexpr int SMEM64  = 2 * 128 * 136 * 2 + 2 * 64 * 136 * 2;   // 104448
    cudaFuncSetAttribute(gemm_mma_kernel<128, false>, cudaFuncAttributeMaxDynamicSharedMemorySize, SMEM128);
    cudaFuncSetAttribute(gemm_mma_kernel<128, true>,  cudaFuncAttributeMaxDynamicSharedMemorySize, SMEM128);
    cudaFuncSetAttribute(gemm_mma_kernel<64,  true>,  cudaFuncAttributeMaxDynamicSharedMemorySize, SMEM64);

    const int* src = ei;
    const int* dst = ei + E;

    const int nb = (n + 255) / 256;
    const int gemm_blocks = (n + 127) / 128;
    const int agg128_blocks = ((n * 32) + 255) / 256;
    const int agg64_blocks  = ((n * 16) + 255) / 256;

    // Launch order: profiled launch (index 3) = layer-1 mma GEMM
    prep_w_kernel<<<160, 256>>>(W1, W2, W3, d_w1h, d_w1l, d_w2h, d_w2l, d_w3h, d_w3l); // 0
    zero_cnt_kernel<<<nb, 256>>>(d_cnt, n);                                            // 1
    count_kernel<<<(E + 255) / 256, 256>>>(d_cnt, dst, E);                             // 2
    gemm_mma_kernel<128, false><<<gemm_blocks, 512, SMEM128>>>(x, d_w1h, d_w1l, d_h, n);// 3 (profiled)
    scan1_kernel<<<nb, 256>>>(d_cnt, d_cursor, d_bsums, d_dis, n);                     // 4
    scan2_kernel<<<1, 1024>>>(d_bsums, nb);                                            // 5
    scan3_kernel<<<nb, 256>>>(d_cursor, d_bsums, d_rowptr, d_cursor, n, E);            // 6
    fill_kernel<<<(E + 255) / 256, 256>>>(src, dst, d_dis, d_cursor, d_esrc, d_ewt, E);// 7

    // Layer 1 aggregate
    agg_kernel<128><<<agg128_blocks, 256>>>(d_rowptr, d_esrc, d_ewt, d_h, d_dis, b1, d_bufA, n);

    // Layer 2
    gemm_mma_kernel<128, true><<<gemm_blocks, 512, SMEM128>>>(d_bufA, d_w2h, d_w2l, d_h, n);
    agg_kernel<128><<<agg128_blocks, 256>>>(d_rowptr, d_esrc, d_ewt, d_h, d_dis, b2, d_bufB, n);

    // Layer 3 (DOUT=64)
    gemm_mma_kernel<64, true><<<gemm_blocks, 512, SMEM64>>>(d_bufB, d_w3h, d_w3l, d_h, n);
    agg_kernel<64><<<agg64_blocks, 256>>>(d_rowptr, d_esrc, d_ewt, d_h, d_dis, b3, d_bufA, n);

    // Decode
    decode_kernel<<<((EL * 16) + 255) / 256, 256>>>(d_bufA, eli, out_hidden, out_logits, EL);
}

// round 7
// speedup vs baseline: 3.3590x; 1.0424x over previous
#include <cuda_runtime.h>
#include <cuda_bf16.h>
#include <cstdio>
#include <cstdint>

// Problem constants: N=100000, E=1.6M, EL=200000
#define NMAX 100000
#define EMAX 1600000

// Scratch (static __device__ arrays — no allocation allowed)
__device__ float g_dis[NMAX];
__device__ int   g_cnt[NMAX];
__device__ int   g_rowptr[NMAX + 1];
__device__ int   g_cursor[NMAX];
__device__ int   g_bsums[1024];
__device__ int   g_esrc[EMAX];
__device__ float g_ewt[EMAX];
__device__ float g_h[NMAX * 128];
__device__ float g_bufA[NMAX * 128];
__device__ float g_bufB[NMAX * 128];
// Transposed bf16 hi/lo weights: Wt[n][k] = W[k][n]
__device__ __nv_bfloat16 g_w1h[128 * 128], g_w1l[128 * 128];
__device__ __nv_bfloat16 g_w2h[128 * 128], g_w2l[128 * 128];
__device__ __nv_bfloat16 g_w3h[64 * 128],  g_w3l[64 * 128];

// ---------------------------------------------------------------------------
// PTX helpers (baseline sm_80+ features only — no tcgen05 in this harness)
// ---------------------------------------------------------------------------
__device__ __forceinline__ uint32_t smem_u32(const void* p) {
    uint32_t a;
    asm("{ .reg .u64 t; cvta.to.shared.u64 t, %1; cvt.u32.u64 %0, t; }" : "=r"(a) : "l"(p));
    return a;
}
__device__ __forceinline__ void ldsm_x4(uint32_t* r, uint32_t addr) {
    asm volatile("ldmatrix.sync.aligned.m8n8.x4.shared.b16 {%0,%1,%2,%3}, [%4];"
                 : "=r"(r[0]), "=r"(r[1]), "=r"(r[2]), "=r"(r[3]) : "r"(addr));
}
__device__ __forceinline__ void mma16816(float* d, const uint32_t* a, uint32_t b0, uint32_t b1) {
    asm volatile("mma.sync.aligned.m16n8k16.row.col.f32.bf16.bf16.f32 "
                 "{%0,%1,%2,%3}, {%4,%5,%6,%7}, {%8,%9}, {%0,%1,%2,%3};"
                 : "+f"(d[0]), "+f"(d[1]), "+f"(d[2]), "+f"(d[3])
                 : "r"(a[0]), "r"(a[1]), "r"(a[2]), "r"(a[3]), "r"(b0), "r"(b1));
}
__device__ __forceinline__ uint32_t pack_bf2(float x, float y) {
    __nv_bfloat162 v;
    v.x = __float2bfloat16(x);
    v.y = __float2bfloat16(y);
    return *reinterpret_cast<uint32_t*>(&v);
}

// ---------------------------------------------------------------------------
// Weight prep: Wt_hi/lo[n*128+k] = bf16split(W[k*DOUT+n])
// ---------------------------------------------------------------------------
__global__ void prep_w_kernel(const float* __restrict__ W1, const float* __restrict__ W2,
                              const float* __restrict__ W3,
                              __nv_bfloat16* __restrict__ w1h, __nv_bfloat16* __restrict__ w1l,
                              __nv_bfloat16* __restrict__ w2h, __nv_bfloat16* __restrict__ w2l,
                              __nv_bfloat16* __restrict__ w3h, __nv_bfloat16* __restrict__ w3l)
{
    int i = blockIdx.x * blockDim.x + threadIdx.x;
    const float* W; __nv_bfloat16 *oh, *ol; int dout, j;
    if (i < 16384)      { W = W1; oh = w1h; ol = w1l; dout = 128; j = i; }
    else if (i < 32768) { W = W2; oh = w2h; ol = w2l; dout = 128; j = i - 16384; }
    else if (i < 40960) { W = W3; oh = w3h; ol = w3l; dout = 64;  j = i - 32768; }
    else return;
    int nn = j >> 7, k = j & 127;
    float w = W[k * dout + nn];
    __nv_bfloat16 hi = __float2bfloat16(w);
    float lo = w - __bfloat162float(hi);
    oh[j] = hi;
    ol[j] = __float2bfloat16(lo);
}

// ---------------------------------------------------------------------------
// mma.sync bf16-split GEMM: h = relu?(in) @ W
// Block: 256 thr, 64 rows x DOUT cols, K=128. Warp grid 2x4, warp tile
// 32 x (DOUT/4). 3 products: Ah*Bh + Ah*Bl + Al*Bh (fp32 accum).
// smem pitch 136 halfwords (272B) -> conflict-free ldmatrix.
// 104KB smem (DOUT=128) -> 2 CTAs/SM; 70KB (DOUT=64) -> 3 CTAs/SM.
// ---------------------------------------------------------------------------
template <int DOUT, bool RELU_IN>
__global__ void __launch_bounds__(256)
gemm_mma_kernel(const float* __restrict__ in, const __nv_bfloat16* __restrict__ wtHi,
                const __nv_bfloat16* __restrict__ wtLo, float* __restrict__ h, int n)
{
    constexpr int THREADS = 256;
    constexpr int ROWS = 64;
    constexpr int K = 128;
    constexpr int PITCH = 136;                   // halfwords per smem row
    constexpr int TN = DOUT / 4;                 // warp tile cols (32 or 16)
    constexpr int NT = TN / 8;                   // n-tiles per warp (4 or 2)
    constexpr int NG = NT / 2;                   // ldmatrix.x4 groups for B (2 or 1)
    // smem halfword offsets
    constexpr int A_HI = 0;
    constexpr int A_LO = ROWS * PITCH;           // 8704
    constexpr int B_HI = 2 * ROWS * PITCH;       // 17408
    constexpr int B_LO = B_HI + DOUT * PITCH;

    extern __shared__ __nv_bfloat16 smem[];
    const int t = threadIdx.x;
    const int row0 = blockIdx.x * ROWS;

    // ---- Stage A (fp32 -> hi/lo bf16, ReLU folded) ----
    const float4* in4 = reinterpret_cast<const float4*>(in);
    #pragma unroll
    for (int i = t; i < ROWS * (K / 4); i += THREADS) {
        int r = i >> 5, c4 = i & 31;
        int gr = row0 + r;
        float4 v = make_float4(0.f, 0.f, 0.f, 0.f);
        if (gr < n) v = in4[(size_t)gr * (K / 4) + c4];
        if (RELU_IN) {
            v.x = fmaxf(v.x, 0.f); v.y = fmaxf(v.y, 0.f);
            v.z = fmaxf(v.z, 0.f); v.w = fmaxf(v.w, 0.f);
        }
        uint32_t h0 = pack_bf2(v.x, v.y);
        uint32_t h1 = pack_bf2(v.z, v.w);
        __nv_bfloat162 hh0 = *reinterpret_cast<__nv_bfloat162*>(&h0);
        __nv_bfloat162 hh1 = *reinterpret_cast<__nv_bfloat162*>(&h1);
        uint32_t l0 = pack_bf2(v.x - __bfloat162float(hh0.x), v.y - __bfloat162float(hh0.y));
        uint32_t l1 = pack_bf2(v.z - __bfloat162float(hh1.x), v.w - __bfloat162float(hh1.y));
        int off = r * PITCH + c4 * 4;
        *reinterpret_cast<uint2*>(smem + A_HI + off) = make_uint2(h0, h1);
        *reinterpret_cast<uint2*>(smem + A_LO + off) = make_uint2(l0, l1);
    }

    // ---- Stage B (transposed bf16 weights, coalesced 16B chunks) ----
    const uint4* wh4 = reinterpret_cast<const uint4*>(wtHi);
    const uint4* wl4 = reinterpret_cast<const uint4*>(wtLo);
    #pragma unroll
    for (int i = t; i < DOUT * 16; i += THREADS) {
        int nn = i >> 4, j = i & 15;
        int off = nn * PITCH + j * 8;
        *reinterpret_cast<uint4*>(smem + B_HI + off) = wh4[i];
        *reinterpret_cast<uint4*>(smem + B_LO + off) = wl4[i];
    }
    __syncthreads();

    // ---- Fragment addresses ----
    const int wid  = t >> 5;
    const int lane = t & 31;
    const int warpM = wid >> 2;   // 0..1
    const int warpN = wid & 3;    // 0..3

    // A ldmatrix.x4: lane -> row (lane%16), k-col (lane/16)*8
    const int aRow = warpM * 32 + (lane & 15);
    const int aCol = (lane >> 4) * 8;
    const uint32_t sb = smem_u32(smem);
    const uint32_t aHiAddr = sb + (uint32_t)(A_HI + aRow * PITCH + aCol) * 2;
    const uint32_t aLoAddr = aHiAddr + (uint32_t)(A_LO - A_HI) * 2;
    // B ldmatrix.x4: covers 2 n-tiles; lane -> n = base + ((lane&16)>>1) + (lane&7),
    // k-col = (lane&8)
    const int bN = warpN * TN + ((lane & 16) >> 1) + (lane & 7);
    const int bK = lane & 8;
    const uint32_t bHiAddr = sb + (uint32_t)(B_HI + bN * PITCH + bK) * 2;
    const uint32_t bLoAddr = bHiAddr + (uint32_t)(DOUT * PITCH) * 2;

    float acc[2][NT][4];
    #pragma unroll
    for (int mt = 0; mt < 2; ++mt)
        #pragma unroll
        for (int nt = 0; nt < NT; ++nt)
            #pragma unroll
            for (int r = 0; r < 4; ++r) acc[mt][nt][r] = 0.f;

    #pragma unroll
    for (int kt = 0; kt < 8; ++kt) {
        const uint32_t ka = kt * 32;          // 16 halfwords = 32 bytes per k-tile
        uint32_t ah[2][4], al[2][4], bh[NG][4], bl[NG][4];
        // Issue ALL ldmatrix up front — maximal scoreboard parallelism
        ldsm_x4(ah[0], aHiAddr + ka);
        ldsm_x4(ah[1], aHiAddr + ka + 16 * PITCH * 2);
        #pragma unroll
        for (int g = 0; g < NG; ++g)
            ldsm_x4(bh[g], bHiAddr + ka + g * 16 * PITCH * 2);
        #pragma unroll
        for (int g = 0; g < NG; ++g)
            ldsm_x4(bl[g], bLoAddr + ka + g * 16 * PITCH * 2);
        ldsm_x4(al[0], aLoAddr + ka);
        ldsm_x4(al[1], aLoAddr + ka + 16 * PITCH * 2);

        // hi * hi
        #pragma unroll
        for (int mt = 0; mt < 2; ++mt)
            #pragma unroll
            for (int g = 0; g < NG; ++g) {
                mma16816(acc[mt][2 * g + 0], ah[mt], bh[g][0], bh[g][1]);
                mma16816(acc[mt][2 * g + 1], ah[mt], bh[g][2], bh[g][3]);
            }
        // hi * lo
        #pragma unroll
        for (int mt = 0; mt < 2; ++mt)
            #pragma unroll
            for (int g = 0; g < NG; ++g) {
                mma16816(acc[mt][2 * g + 0], ah[mt], bl[g][0], bl[g][1]);
                mma16816(acc[mt][2 * g + 1], ah[mt], bl[g][2], bl[g][3]);
            }
        // lo * hi
        #pragma unroll
        for (int mt = 0; mt < 2; ++mt)
            #pragma unroll
            for (int g = 0; g < NG; ++g) {
                mma16816(acc[mt][2 * g + 0], al[mt], bh[g][0], bh[g][1]);
                mma16816(acc[mt][2 * g + 1], al[mt], bh[g][2], bh[g][3]);
            }
    }

    // ---- Epilogue: direct float2 stores from fragments ----
    float2* h2 = reinterpret_cast<float2*>(h);
    #pragma unroll
    for (int mt = 0; mt < 2; ++mt) {
        #pragma unroll
        for (int nt = 0; nt < NT; ++nt) {
            int r = row0 + warpM * 32 + mt * 16 + (lane >> 2);
            int c = warpN * TN + nt * 8 + 2 * (lane & 3);
            if (r < n)
                h2[(size_t)r * (DOUT / 2) + c / 2] = make_float2(acc[mt][nt][0], acc[mt][nt][1]);
            if (r + 8 < n)
                h2[(size_t)(r + 8) * (DOUT / 2) + c / 2] = make_float2(acc[mt][nt][2], acc[mt][nt][3]);
        }
    }
}

// ---------------------------------------------------------------------------
// CSR build kernels
// ---------------------------------------------------------------------------
__global__ void zero_cnt_kernel(int* __restrict__ cnt, int n) {
    int i = blockIdx.x * blockDim.x + threadIdx.x;
    if (i < n) cnt[i] = 0;
}

__global__ void count_kernel(int* __restrict__ cnt, const int* __restrict__ dst, int E) {
    int e = blockIdx.x * blockDim.x + threadIdx.x;
    if (e < E) atomicAdd(&cnt[dst[e]], 1);
}

__global__ void scan1_kernel(const int* __restrict__ cnt, int* __restrict__ part,
                             int* __restrict__ sums, float* __restrict__ dis, int n) {
    __shared__ int sm[256];
    int t = threadIdx.x;
    int i = blockIdx.x * 256 + t;
    int v = (i < n) ? cnt[i] : 0;
    if (i < n) dis[i] = rsqrtf((float)(v + 1));
    sm[t] = v;
    __syncthreads();
    #pragma unroll
    for (int off = 1; off < 256; off <<= 1) {
        int a = (t >= off) ? sm[t - off] : 0;
        __syncthreads();
        sm[t] += a;
        __syncthreads();
    }
    if (i < n) part[i] = sm[t] - v;
    if (t == 255) sums[blockIdx.x] = sm[255];
}

__global__ void scan2_kernel(int* __restrict__ sums, int nb) {
    __shared__ int sm[1024];
    int t = threadIdx.x;
    int v = (t < nb) ? sums[t] : 0;
    sm[t] = v;
    __syncthreads();
    #pragma unroll
    for (int off = 1; off < 1024; off <<= 1) {
        int a = (t >= off) ? sm[t - off] : 0;
        __syncthreads();
        sm[t] += a;
        __syncthreads();
    }
    if (t < nb) sums[t] = sm[t] - v;
}

__global__ void scan3_kernel(const int* __restrict__ part, const int* __restrict__ sums,
                             int* __restrict__ row_ptr, int* __restrict__ cursor,
                             int n, int E) {
    int i = blockIdx.x * blockDim.x + threadIdx.x;
    if (i < n) {
        int v = part[i] + sums[i >> 8];
        row_ptr[i] = v;
        cursor[i] = v;
    }
    if (i == 0) row_ptr[n] = E;
}

__global__ void fill_kernel(const int* __restrict__ src, const int* __restrict__ dst,
                            const float* __restrict__ dis,
                            int* __restrict__ cursor, int* __restrict__ esrc,
                            float* __restrict__ ewt, int E) {
    int e = blockIdx.x * blockDim.x + threadIdx.x;
    if (e >= E) return;
    int s = src[e];
    int d = dst[e];
    int pos = atomicAdd(&cursor[d], 1);
    esrc[pos] = s;
    ewt[pos] = dis[s] * dis[d];
}

// ---------------------------------------------------------------------------
// CSR gather-aggregate with fused self-loop + bias
// ---------------------------------------------------------------------------
template <int D>
__global__ void __launch_bounds__(256)
agg_kernel(const int* __restrict__ rp, const int* __restrict__ esrc,
           const float* __restrict__ ewt, const float* __restrict__ h,
           const float* __restrict__ dis, const float* __restrict__ bias,
           float* __restrict__ out, int n)
{
    constexpr int G = D / 4;
    int tid = blockIdx.x * blockDim.x + threadIdx.x;
    int node = tid / G;
    int li   = tid % G;
    if (node >= n) return;

    int beg = rp[node];
    int end = rp[node + 1];

    const float4* h4 = reinterpret_cast<const float4*>(h);

    float d = dis[node];
    float dd = d * d;
    float4 hv = h4[(size_t)node * G + li];
    float4 b4 = reinterpret_cast<const float4*>(bias)[li];
    float4 acc;
    acc.x = fmaf(dd, hv.x, b4.x);
    acc.y = fmaf(dd, hv.y, b4.y);
    acc.z = fmaf(dd, hv.z, b4.z);
    acc.w = fmaf(dd, hv.w, b4.w);

    int j = beg;
    for (; j + 4 <= end; j += 4) {
        int s0 = esrc[j], s1 = esrc[j + 1], s2 = esrc[j + 2], s3 = esrc[j + 3];
        float w0 = ewt[j], w1 = ewt[j + 1], w2 = ewt[j + 2], w3 = ewt[j + 3];
        float4 v0 = h4[(size_t)s0 * G + li];
        float4 v1 = h4[(size_t)s1 * G + li];
        float4 v2 = h4[(size_t)s2 * G + li];
        float4 v3 = h4[(size_t)s3 * G + li];
        acc.x = fmaf(w0, v0.x, fmaf(w1, v1.x, fmaf(w2, v2.x, fmaf(w3, v3.x, acc.x))));
        acc.y = fmaf(w0, v0.y, fmaf(w1, v1.y, fmaf(w2, v2.y, fmaf(w3, v3.y, acc.y))));
        acc.z = fmaf(w0, v0.z, fmaf(w1, v1.z, fmaf(w2, v2.z, fmaf(w3, v3.z, acc.z))));
        acc.w = fmaf(w0, v0.w, fmaf(w1, v1.w, fmaf(w2, v2.w, fmaf(w3, v3.w, acc.w))));
    }
    for (; j < end; ++j) {
        int s = esrc[j];
        float w = ewt[j];
        float4 v = h4[(size_t)s * G + li];
        acc.x = fmaf(w, v.x, acc.x);
        acc.y = fmaf(w, v.y, acc.y);
        acc.z = fmaf(w, v.z, acc.z);
        acc.w = fmaf(w, v.w, acc.w);
    }

    reinterpret_cast<float4*>(out)[(size_t)node * G + li] = acc;
}

// ---------------------------------------------------------------------------
// Decode
// ---------------------------------------------------------------------------
__global__ void __launch_bounds__(256)
decode_kernel(const float* __restrict__ z, const int* __restrict__ eli,
              float* __restrict__ outh, float* __restrict__ outl, int EL)
{
    int tid = blockIdx.x * blockDim.x + threadIdx.x;
    int eid = tid >> 4;
    int li  = tid & 15;
    int lane = threadIdx.x & 31;
    unsigned mask = 0xFFFFu << (lane & 16);

    if (eid >= EL) return;

    int s = eli[eid];
    int t = eli[EL + eid];
    const float4* z4 = reinterpret_cast<const float4*>(z);
    float4 a = z4[(size_t)s * 16 + li];
    float4 b = z4[(size_t)t * 16 + li];

    float4 hh;
    hh.x = a.x * b.x; hh.y = a.y * b.y; hh.z = a.z * b.z; hh.w = a.w * b.w;

    float sum = hh.x + hh.y + hh.z + hh.w;
    float sq  = hh.x * hh.x + hh.y * hh.y + hh.z * hh.z + hh.w * hh.w;

    #pragma unroll
    for (int off = 8; off > 0; off >>= 1) {
        sum += __shfl_xor_sync(mask, sum, off);
        sq  += __shfl_xor_sync(mask, sq,  off);
    }

    float nrm = sqrtf(sq);
    float inv = 1.0f / fmaxf(nrm, 1e-12f);
    float4 o;
    o.x = hh.x * inv; o.y = hh.y * inv; o.z = hh.z * inv; o.w = hh.w * inv;
    reinterpret_cast<float4*>(outh)[(size_t)eid * 16 + li] = o;
    if (li == 0) outl[eid] = sum;
}

// ---------------------------------------------------------------------------
// Launch
// ---------------------------------------------------------------------------
extern "C" void kernel_launch(void* const* d_in, const int* in_sizes, int n_in,
                              void* d_out, int out_size)
{
    const float* x   = (const float*)d_in[0];
    const float* W1  = (const float*)d_in[1];
    const float* b1  = (const float*)d_in[2];
    const float* W2  = (const float*)d_in[3];
    const float* b2  = (const float*)d_in[4];
    const float* W3  = (const float*)d_in[5];
    const float* b3  = (const float*)d_in[6];
    const int*   ei  = (const int*)d_in[7];
    const int*   eli = (const int*)d_in[8];

    const int n  = in_sizes[0] / 128;
    const int E  = in_sizes[7] / 2;
    const int EL = in_sizes[8] / 2;

    float* out = (float*)d_out;
    float* out_hidden = out;
    float* out_logits = out + (size_t)EL * 64;

    float *d_dis, *d_h, *d_bufA, *d_bufB, *d_ewt;
    int *d_cnt, *d_rowptr, *d_cursor, *d_bsums, *d_esrc;
    __nv_bfloat16 *d_w1h, *d_w1l, *d_w2h, *d_w2l, *d_w3h, *d_w3l;
    cudaGetSymbolAddress((void**)&d_dis,    g_dis);
    cudaGetSymbolAddress((void**)&d_cnt,    g_cnt);
    cudaGetSymbolAddress((void**)&d_rowptr, g_rowptr);
    cudaGetSymbolAddress((void**)&d_cursor, g_cursor);
    cudaGetSymbolAddress((void**)&d_bsums,  g_bsums);
    cudaGetSymbolAddress((void**)&d_esrc,   g_esrc);
    cudaGetSymbolAddress((void**)&d_ewt,    g_ewt);
    cudaGetSymbolAddress((void**)&d_h,      g_h);
    cudaGetSymbolAddress((void**)&d_bufA,   g_bufA);
    cudaGetSymbolAddress((void**)&d_bufB,   g_bufB);
    cudaGetSymbolAddress((void**)&d_w1h,    g_w1h);
    cudaGetSymbolAddress((void**)&d_w1l,    g_w1l);
    cudaGetSymbolAddress((void**)&d_w2h,    g_w2h);
    cudaGetSymbolAddress((void**)&d_w2l,    g_w2l);
    cudaGetSymbolAddress((void**)&d_w3h,    g_w3h);
    cudaGetSymbolAddress((void**)&d_w3l,    g_w3l);

    // smem: A hi/lo (2*64*136*2) + B hi/lo (2*DOUT*136*2)
    constexpr int SMEM128 = 2 * 64 * 136 * 2 + 2 * 128 * 136 * 2;  // 104448
    constexpr int SMEM64  = 2 * 64 * 136 * 2 + 2 * 64 * 136 * 2;   // 69632
    cudaFuncSetAttribute(gemm_mma_kernel<128, false>, cudaFuncAttributeMaxDynamicSharedMemorySize, SMEM128);
    cudaFuncSetAttribute(gemm_mma_kernel<128, true>,  cudaFuncAttributeMaxDynamicSharedMemorySize, SMEM128);
    cudaFuncSetAttribute(gemm_mma_kernel<64,  true>,  cudaFuncAttributeMaxDynamicSharedMemorySize, SMEM64);

    const int* src = ei;
    const int* dst = ei + E;

    const int nb = (n + 255) / 256;
    const int gemm_blocks = (n + 63) / 64;
    const int agg128_blocks = ((n * 32) + 255) / 256;
    const int agg64_blocks  = ((n * 16) + 255) / 256;

    // Launch order: profiled launch (index 3) = layer-1 mma GEMM
    prep_w_kernel<<<160, 256>>>(W1, W2, W3, d_w1h, d_w1l, d_w2h, d_w2l, d_w3h, d_w3l); // 0
    zero_cnt_kernel<<<nb, 256>>>(d_cnt, n);                                            // 1
    count_kernel<<<(E + 255) / 256, 256>>>(d_cnt, dst, E);                             // 2
    gemm_mma_kernel<128, false><<<gemm_blocks, 256, SMEM128>>>(x, d_w1h, d_w1l, d_h, n);// 3 (profiled)
    scan1_kernel<<<nb, 256>>>(d_cnt, d_cursor, d_bsums, d_dis, n);                     // 4
    scan2_kernel<<<1, 1024>>>(d_bsums, nb);                                            // 5
    scan3_kernel<<<nb, 256>>>(d_cursor, d_bsums, d_rowptr, d_cursor, n, E);            // 6
    fill_kernel<<<(E + 255) / 256, 256>>>(src, dst, d_dis, d_cursor, d_esrc, d_ewt, E);// 7

    // Layer 1 aggregate
    agg_kernel<128><<<agg128_blocks, 256>>>(d_rowptr, d_esrc, d_ewt, d_h, d_dis, b1, d_bufA, n);

    // Layer 2
    gemm_mma_kernel<128, true><<<gemm_blocks, 256, SMEM128>>>(d_bufA, d_w2h, d_w2l, d_h, n);
    agg_kernel<128><<<agg128_blocks, 256>>>(d_rowptr, d_esrc, d_ewt, d_h, d_dis, b2, d_bufB, n);

    // Layer 3 (DOUT=64)
    gemm_mma_kernel<64, true><<<gemm_blocks, 256, SMEM64>>>(d_bufB, d_w3h, d_w3l, d_h, n);
    agg_kernel<64><<<agg64_blocks, 256>>>(d_rowptr, d_esrc, d_ewt, d_h, d_dis, b3, d_bufA, n);

    // Decode
    decode_kernel<<<((EL * 16) + 255) / 256, 256>>>(d_bufA, eli, out_hidden, out_logits, EL);
}

// round 8
// speedup vs baseline: 3.4932x; 1.0400x over previous
#include <cuda_runtime.h>
#include <cuda_bf16.h>
#include <cstdio>
#include <cstdint>

// Problem constants: N=100000, E=1.6M, EL=200000
#define NMAX 100000
#define EMAX 1600000

// Scratch (static __device__ arrays — no allocation allowed)
__device__ float g_dis[NMAX];
__device__ int   g_cnt[NMAX];
__device__ int   g_rowptr[NMAX + 1];
__device__ int   g_cursor[NMAX];
__device__ int   g_bsums[1024];
__device__ int   g_esrc[EMAX];
__device__ float g_ewt[EMAX];
__device__ float g_h[NMAX * 128];
__device__ float g_bufA[NMAX * 128];
__device__ float g_bufB[NMAX * 128];
// Fragment-ordered bf16 hi/lo weights (mma.sync .col B fragments)
// entry (ntile, ktile, lane) -> uint2 {b0, b1}
__device__ __nv_bfloat16 g_w1h[128 * 128], g_w1l[128 * 128];
__device__ __nv_bfloat16 g_w2h[128 * 128], g_w2l[128 * 128];
__device__ __nv_bfloat16 g_w3h[64 * 128],  g_w3l[64 * 128];

// ---------------------------------------------------------------------------
// PTX helpers (baseline sm_80+ features only — no tcgen05 in this harness)
// ---------------------------------------------------------------------------
__device__ __forceinline__ uint32_t smem_u32(const void* p) {
    uint32_t a;
    asm("{ .reg .u64 t; cvta.to.shared.u64 t, %1; cvt.u32.u64 %0, t; }" : "=r"(a) : "l"(p));
    return a;
}
__device__ __forceinline__ void ldsm_x4(uint32_t* r, uint32_t addr) {
    asm volatile("ldmatrix.sync.aligned.m8n8.x4.shared.b16 {%0,%1,%2,%3}, [%4];"
                 : "=r"(r[0]), "=r"(r[1]), "=r"(r[2]), "=r"(r[3]) : "r"(addr));
}
__device__ __forceinline__ void mma16816(float* d, const uint32_t* a, uint32_t b0, uint32_t b1) {
    asm volatile("mma.sync.aligned.m16n8k16.row.col.f32.bf16.bf16.f32 "
                 "{%0,%1,%2,%3}, {%4,%5,%6,%7}, {%8,%9}, {%0,%1,%2,%3};"
                 : "+f"(d[0]), "+f"(d[1]), "+f"(d[2]), "+f"(d[3])
                 : "r"(a[0]), "r"(a[1]), "r"(a[2]), "r"(a[3]), "r"(b0), "r"(b1));
}
__device__ __forceinline__ uint32_t pack_bf2(float x, float y) {
    __nv_bfloat162 v;
    v.x = __float2bfloat16(x);
    v.y = __float2bfloat16(y);
    return *reinterpret_cast<uint32_t*>(&v);
}

// ---------------------------------------------------------------------------
// Weight prep -> fragment-ordered hi/lo arrays.
// Fragment entry j = (ntile*8 + ktile)*32 + lane:
//   n  = ntile*8 + lane/4
//   k0 = ktile*16 + (lane%4)*2
//   b0 = pack(B[k0][n], B[k0+1][n]),  b1 = pack(B[k0+8][n], B[k0+9][n])
// (B[k][n] = W[k*DOUT+n]); hi = bf16(w), lo = bf16(w - hi)
// ---------------------------------------------------------------------------
__global__ void prep_w_kernel(const float* __restrict__ W1, const float* __restrict__ W2,
                              const float* __restrict__ W3,
                              __nv_bfloat16* __restrict__ w1h, __nv_bfloat16* __restrict__ w1l,
                              __nv_bfloat16* __restrict__ w2h, __nv_bfloat16* __restrict__ w2l,
                              __nv_bfloat16* __restrict__ w3h, __nv_bfloat16* __restrict__ w3l)
{
    int i = blockIdx.x * blockDim.x + threadIdx.x;
    // entries: L1 = 16nt*8kt*32 = 4096, L2 = 4096, L3 = 8nt*8kt*32 = 2048
    const float* W; uint2 *oh, *ol; int dout, j;
    if (i < 4096)       { W = W1; oh = (uint2*)w1h; ol = (uint2*)w1l; dout = 128; j = i; }
    else if (i < 8192)  { W = W2; oh = (uint2*)w2h; ol = (uint2*)w2l; dout = 128; j = i - 4096; }
    else if (i < 10240) { W = W3; oh = (uint2*)w3h; ol = (uint2*)w3l; dout = 64;  j = i - 8192; }
    else return;

    int lane  = j & 31;
    int ktile = (j >> 5) & 7;
    int ntile = j >> 8;
    int n  = ntile * 8 + (lane >> 2);
    int k0 = ktile * 16 + (lane & 3) * 2;

    float w00 = W[(k0 + 0) * dout + n];
    float w01 = W[(k0 + 1) * dout + n];
    float w10 = W[(k0 + 8) * dout + n];
    float w11 = W[(k0 + 9) * dout + n];

    __nv_bfloat16 h00 = __float2bfloat16(w00), h01 = __float2bfloat16(w01);
    __nv_bfloat16 h10 = __float2bfloat16(w10), h11 = __float2bfloat16(w11);

    uint2 hv, lv;
    hv.x = pack_bf2(w00, w01);
    hv.y = pack_bf2(w10, w11);
    lv.x = pack_bf2(w00 - __bfloat162float(h00), w01 - __bfloat162float(h01));
    lv.y = pack_bf2(w10 - __bfloat162float(h10), w11 - __bfloat162float(h11));
    oh[j] = hv;
    ol[j] = lv;
}

// ---------------------------------------------------------------------------
// mma.sync bf16-split GEMM: h = relu?(in) @ W
// Block: 256 thr, 64 rows x DOUT cols, K=128. Warp grid 2x4.
// A staged in smem (hi/lo, 34.8KB total) + ldmatrix; B fragments LDG'd
// directly from fragment-ordered global arrays (L1/L2-resident, 32KB/layer).
// 3 products: Ah*Bh + Ah*Bl + Al*Bh (fp32 accum).
// ---------------------------------------------------------------------------
template <int DOUT, bool RELU_IN>
__global__ void __launch_bounds__(256, 4)
gemm_mma_kernel(const float* __restrict__ in, const __nv_bfloat16* __restrict__ wtHi,
                const __nv_bfloat16* __restrict__ wtLo, float* __restrict__ h, int n)
{
    constexpr int THREADS = 256;
    constexpr int ROWS = 64;
    constexpr int K = 128;
    constexpr int PITCH = 136;                   // halfwords per smem row
    constexpr int TN = DOUT / 4;                 // warp tile cols (32 or 16)
    constexpr int NT = TN / 8;                   // n-tiles per warp (4 or 2)
    // smem halfword offsets (A only)
    constexpr int A_HI = 0;
    constexpr int A_LO = ROWS * PITCH;           // 8704

    extern __shared__ __nv_bfloat16 smem[];
    const int t = threadIdx.x;
    const int row0 = blockIdx.x * ROWS;

    // ---- Stage A (fp32 -> hi/lo bf16, ReLU folded) ----
    const float4* in4 = reinterpret_cast<const float4*>(in);
    #pragma unroll
    for (int i = t; i < ROWS * (K / 4); i += THREADS) {
        int r = i >> 5, c4 = i & 31;
        int gr = row0 + r;
        float4 v = make_float4(0.f, 0.f, 0.f, 0.f);
        if (gr < n) v = in4[(size_t)gr * (K / 4) + c4];
        if (RELU_IN) {
            v.x = fmaxf(v.x, 0.f); v.y = fmaxf(v.y, 0.f);
            v.z = fmaxf(v.z, 0.f); v.w = fmaxf(v.w, 0.f);
        }
        uint32_t h0 = pack_bf2(v.x, v.y);
        uint32_t h1 = pack_bf2(v.z, v.w);
        __nv_bfloat162 hh0 = *reinterpret_cast<__nv_bfloat162*>(&h0);
        __nv_bfloat162 hh1 = *reinterpret_cast<__nv_bfloat162*>(&h1);
        uint32_t l0 = pack_bf2(v.x - __bfloat162float(hh0.x), v.y - __bfloat162float(hh0.y));
        uint32_t l1 = pack_bf2(v.z - __bfloat162float(hh1.x), v.w - __bfloat162float(hh1.y));
        int off = r * PITCH + c4 * 4;
        *reinterpret_cast<uint2*>(smem + A_HI + off) = make_uint2(h0, h1);
        *reinterpret_cast<uint2*>(smem + A_LO + off) = make_uint2(l0, l1);
    }
    __syncthreads();

    // ---- Fragment addresses ----
    const int wid  = t >> 5;
    const int lane = t & 31;
    const int warpM = wid >> 2;   // 0..1
    const int warpN = wid & 3;    // 0..3

    // A ldmatrix.x4: lane -> row (lane%16), k-col (lane/16)*8
    const int aRow = warpM * 32 + (lane & 15);
    const int aCol = (lane >> 4) * 8;
    const uint32_t sb = smem_u32(smem);
    const uint32_t aHiAddr = sb + (uint32_t)(A_HI + aRow * PITCH + aCol) * 2;
    const uint32_t aLoAddr = aHiAddr + (uint32_t)(A_LO - A_HI) * 2;

    // B fragment arrays: entry ((ntile*8 + ktile)*32 + lane) as uint2
    const uint2* fH = reinterpret_cast<const uint2*>(wtHi);
    const uint2* fL = reinterpret_cast<const uint2*>(wtLo);
    const int fbase = (warpN * NT) * 256 + lane;   // ntile stride = 8*32 = 256

    float acc[2][NT][4];
    #pragma unroll
    for (int mt = 0; mt < 2; ++mt)
        #pragma unroll
        for (int nt = 0; nt < NT; ++nt)
            #pragma unroll
            for (int r = 0; r < 4; ++r) acc[mt][nt][r] = 0.f;

    #pragma unroll
    for (int kt = 0; kt < 8; ++kt) {
        const uint32_t ka = kt * 32;          // 16 halfwords = 32 bytes per k-tile
        uint32_t ah[2][4], al[2][4];
        uint2 bh[NT], bl[NT];
        // Issue all loads up front — maximal scoreboard parallelism
        ldsm_x4(ah[0], aHiAddr + ka);
        ldsm_x4(ah[1], aHiAddr + ka + 16 * PITCH * 2);
        #pragma unroll
        for (int nt = 0; nt < NT; ++nt) bh[nt] = __ldg(&fH[fbase + nt * 256 + kt * 32]);
        #pragma unroll
        for (int nt = 0; nt < NT; ++nt) bl[nt] = __ldg(&fL[fbase + nt * 256 + kt * 32]);
        ldsm_x4(al[0], aLoAddr + ka);
        ldsm_x4(al[1], aLoAddr + ka + 16 * PITCH * 2);

        // hi * hi
        #pragma unroll
        for (int mt = 0; mt < 2; ++mt)
            #pragma unroll
            for (int nt = 0; nt < NT; ++nt)
                mma16816(acc[mt][nt], ah[mt], bh[nt].x, bh[nt].y);
        // hi * lo
        #pragma unroll
        for (int mt = 0; mt < 2; ++mt)
            #pragma unroll
            for (int nt = 0; nt < NT; ++nt)
                mma16816(acc[mt][nt], ah[mt], bl[nt].x, bl[nt].y);
        // lo * hi
        #pragma unroll
        for (int mt = 0; mt < 2; ++mt)
            #pragma unroll
            for (int nt = 0; nt < NT; ++nt)
                mma16816(acc[mt][nt], al[mt], bh[nt].x, bh[nt].y);
    }

    // ---- Epilogue: direct float2 stores from fragments ----
    float2* h2 = reinterpret_cast<float2*>(h);
    #pragma unroll
    for (int mt = 0; mt < 2; ++mt) {
        #pragma unroll
        for (int nt = 0; nt < NT; ++nt) {
            int r = row0 + warpM * 32 + mt * 16 + (lane >> 2);
            int c = warpN * TN + nt * 8 + 2 * (lane & 3);
            if (r < n)
                h2[(size_t)r * (DOUT / 2) + c / 2] = make_float2(acc[mt][nt][0], acc[mt][nt][1]);
            if (r + 8 < n)
                h2[(size_t)(r + 8) * (DOUT / 2) + c / 2] = make_float2(acc[mt][nt][2], acc[mt][nt][3]);
        }
    }
}

// ---------------------------------------------------------------------------
// CSR build kernels
// ---------------------------------------------------------------------------
__global__ void zero_cnt_kernel(int* __restrict__ cnt, int n) {
    int i = blockIdx.x * blockDim.x + threadIdx.x;
    if (i < n) cnt[i] = 0;
}

__global__ void count_kernel(int* __restrict__ cnt, const int* __restrict__ dst, int E) {
    int e = blockIdx.x * blockDim.x + threadIdx.x;
    if (e < E) atomicAdd(&cnt[dst[e]], 1);
}

__global__ void scan1_kernel(const int* __restrict__ cnt, int* __restrict__ part,
                             int* __restrict__ sums, float* __restrict__ dis, int n) {
    __shared__ int sm[256];
    int t = threadIdx.x;
    int i = blockIdx.x * 256 + t;
    int v = (i < n) ? cnt[i] : 0;
    if (i < n) dis[i] = rsqrtf((float)(v + 1));
    sm[t] = v;
    __syncthreads();
    #pragma unroll
    for (int off = 1; off < 256; off <<= 1) {
        int a = (t >= off) ? sm[t - off] : 0;
        __syncthreads();
        sm[t] += a;
        __syncthreads();
    }
    if (i < n) part[i] = sm[t] - v;
    if (t == 255) sums[blockIdx.x] = sm[255];
}

__global__ void scan2_kernel(int* __restrict__ sums, int nb) {
    __shared__ int sm[1024];
    int t = threadIdx.x;
    int v = (t < nb) ? sums[t] : 0;
    sm[t] = v;
    __syncthreads();
    #pragma unroll
    for (int off = 1; off < 1024; off <<= 1) {
        int a = (t >= off) ? sm[t - off] : 0;
        __syncthreads();
        sm[t] += a;
        __syncthreads();
    }
    if (t < nb) sums[t] = sm[t] - v;
}

__global__ void scan3_kernel(const int* __restrict__ part, const int* __restrict__ sums,
                             int* __restrict__ row_ptr, int* __restrict__ cursor,
                             int n, int E) {
    int i = blockIdx.x * blockDim.x + threadIdx.x;
    if (i < n) {
        int v = part[i] + sums[i >> 8];
        row_ptr[i] = v;
        cursor[i] = v;
    }
    if (i == 0) row_ptr[n] = E;
}

__global__ void fill_kernel(const int* __restrict__ src, const int* __restrict__ dst,
                            const float* __restrict__ dis,
                            int* __restrict__ cursor, int* __restrict__ esrc,
                            float* __restrict__ ewt, int E) {
    int e = blockIdx.x * blockDim.x + threadIdx.x;
    if (e >= E) return;
    int s = src[e];
    int d = dst[e];
    int pos = atomicAdd(&cursor[d], 1);
    esrc[pos] = s;
    ewt[pos] = dis[s] * dis[d];
}

// ---------------------------------------------------------------------------
// CSR gather-aggregate with fused self-loop + bias
// ---------------------------------------------------------------------------
template <int D>
__global__ void __launch_bounds__(256)
agg_kernel(const int* __restrict__ rp, const int* __restrict__ esrc,
           const float* __restrict__ ewt, const float* __restrict__ h,
           const float* __restrict__ dis, const float* __restrict__ bias,
           float* __restrict__ out, int n)
{
    constexpr int G = D / 4;
    int tid = blockIdx.x * blockDim.x + threadIdx.x;
    int node = tid / G;
    int li   = tid % G;
    if (node >= n) return;

    int beg = rp[node];
    int end = rp[node + 1];

    const float4* h4 = reinterpret_cast<const float4*>(h);

    float d = dis[node];
    float dd = d * d;
    float4 hv = h4[(size_t)node * G + li];
    float4 b4 = reinterpret_cast<const float4*>(bias)[li];
    float4 acc;
    acc.x = fmaf(dd, hv.x, b4.x);
    acc.y = fmaf(dd, hv.y, b4.y);
    acc.z = fmaf(dd, hv.z, b4.z);
    acc.w = fmaf(dd, hv.w, b4.w);

    int j = beg;
    for (; j + 4 <= end; j += 4) {
        int s0 = esrc[j], s1 = esrc[j + 1], s2 = esrc[j + 2], s3 = esrc[j + 3];
        float w0 = ewt[j], w1 = ewt[j + 1], w2 = ewt[j + 2], w3 = ewt[j + 3];
        float4 v0 = h4[(size_t)s0 * G + li];
        float4 v1 = h4[(size_t)s1 * G + li];
        float4 v2 = h4[(size_t)s2 * G + li];
        float4 v3 = h4[(size_t)s3 * G + li];
        acc.x = fmaf(w0, v0.x, fmaf(w1, v1.x, fmaf(w2, v2.x, fmaf(w3, v3.x, acc.x))));
        acc.y = fmaf(w0, v0.y, fmaf(w1, v1.y, fmaf(w2, v2.y, fmaf(w3, v3.y, acc.y))));
        acc.z = fmaf(w0, v0.z, fmaf(w1, v1.z, fmaf(w2, v2.z, fmaf(w3, v3.z, acc.z))));
        acc.w = fmaf(w0, v0.w, fmaf(w1, v1.w, fmaf(w2, v2.w, fmaf(w3, v3.w, acc.w))));
    }
    for (; j < end; ++j) {
        int s = esrc[j];
        float w = ewt[j];
        float4 v = h4[(size_t)s * G + li];
        acc.x = fmaf(w, v.x, acc.x);
        acc.y = fmaf(w, v.y, acc.y);
        acc.z = fmaf(w, v.z, acc.z);
        acc.w = fmaf(w, v.w, acc.w);
    }

    reinterpret_cast<float4*>(out)[(size_t)node * G + li] = acc;
}

// ---------------------------------------------------------------------------
// Decode
// ---------------------------------------------------------------------------
__global__ void __launch_bounds__(256)
decode_kernel(const float* __restrict__ z, const int* __restrict__ eli,
              float* __restrict__ outh, float* __restrict__ outl, int EL)
{
    int tid = blockIdx.x * blockDim.x + threadIdx.x;
    int eid = tid >> 4;
    int li  = tid & 15;
    int lane = threadIdx.x & 31;
    unsigned mask = 0xFFFFu << (lane & 16);

    if (eid >= EL) return;

    int s = eli[eid];
    int t = eli[EL + eid];
    const float4* z4 = reinterpret_cast<const float4*>(z);
    float4 a = z4[(size_t)s * 16 + li];
    float4 b = z4[(size_t)t * 16 + li];

    float4 hh;
    hh.x = a.x * b.x; hh.y = a.y * b.y; hh.z = a.z * b.z; hh.w = a.w * b.w;

    float sum = hh.x + hh.y + hh.z + hh.w;
    float sq  = hh.x * hh.x + hh.y * hh.y + hh.z * hh.z + hh.w * hh.w;

    #pragma unroll
    for (int off = 8; off > 0; off >>= 1) {
        sum += __shfl_xor_sync(mask, sum, off);
        sq  += __shfl_xor_sync(mask, sq,  off);
    }

    float nrm = sqrtf(sq);
    float inv = 1.0f / fmaxf(nrm, 1e-12f);
    float4 o;
    o.x = hh.x * inv; o.y = hh.y * inv; o.z = hh.z * inv; o.w = hh.w * inv;
    reinterpret_cast<float4*>(outh)[(size_t)eid * 16 + li] = o;
    if (li == 0) outl[eid] = sum;
}

// ---------------------------------------------------------------------------
// Launch
// ---------------------------------------------------------------------------
extern "C" void kernel_launch(void* const* d_in, const int* in_sizes, int n_in,
                              void* d_out, int out_size)
{
    const float* x   = (const float*)d_in[0];
    const float* W1  = (const float*)d_in[1];
    const float* b1  = (const float*)d_in[2];
    const float* W2  = (const float*)d_in[3];
    const float* b2  = (const float*)d_in[4];
    const float* W3  = (const float*)d_in[5];
    const float* b3  = (const float*)d_in[6];
    const int*   ei  = (const int*)d_in[7];
    const int*   eli = (const int*)d_in[8];

    const int n  = in_sizes[0] / 128;
    const int E  = in_sizes[7] / 2;
    const int EL = in_sizes[8] / 2;

    float* out = (float*)d_out;
    float* out_hidden = out;
    float* out_logits = out + (size_t)EL * 64;

    float *d_dis, *d_h, *d_bufA, *d_bufB, *d_ewt;
    int *d_cnt, *d_rowptr, *d_cursor, *d_bsums, *d_esrc;
    __nv_bfloat16 *d_w1h, *d_w1l, *d_w2h, *d_w2l, *d_w3h, *d_w3l;
    cudaGetSymbolAddress((void**)&d_dis,    g_dis);
    cudaGetSymbolAddress((void**)&d_cnt,    g_cnt);
    cudaGetSymbolAddress((void**)&d_rowptr, g_rowptr);
    cudaGetSymbolAddress((void**)&d_cursor, g_cursor);
    cudaGetSymbolAddress((void**)&d_bsums,  g_bsums);
    cudaGetSymbolAddress((void**)&d_esrc,   g_esrc);
    cudaGetSymbolAddress((void**)&d_ewt,    g_ewt);
    cudaGetSymbolAddress((void**)&d_h,      g_h);
    cudaGetSymbolAddress((void**)&d_bufA,   g_bufA);
    cudaGetSymbolAddress((void**)&d_bufB,   g_bufB);
    cudaGetSymbolAddress((void**)&d_w1h,    g_w1h);
    cudaGetSymbolAddress((void**)&d_w1l,    g_w1l);
    cudaGetSymbolAddress((void**)&d_w2h,    g_w2h);
    cudaGetSymbolAddress((void**)&d_w2l,    g_w2l);
    cudaGetSymbolAddress((void**)&d_w3h,    g_w3h);
    cudaGetSymbolAddress((void**)&d_w3l,    g_w3l);

    // smem: A hi/lo only (2*64*136*2 B)
    constexpr int SMEM_A = 2 * 64 * 136 * 2;   // 34816
    cudaFuncSetAttribute(gemm_mma_kernel<128, false>, cudaFuncAttributeMaxDynamicSharedMemorySize, SMEM_A);
    cudaFuncSetAttribute(gemm_mma_kernel<128, true>,  cudaFuncAttributeMaxDynamicSharedMemorySize, SMEM_A);
    cudaFuncSetAttribute(gemm_mma_kernel<64,  true>,  cudaFuncAttributeMaxDynamicSharedMemorySize, SMEM_A);

    const int* src = ei;
    const int* dst = ei + E;

    const int nb = (n + 255) / 256;
    const int gemm_blocks = (n + 63) / 64;
    const int agg128_blocks = ((n * 32) + 255) / 256;
    const int agg64_blocks  = ((n * 16) + 255) / 256;

    // Launch order: profiled launch (index 3) = layer-1 mma GEMM
    prep_w_kernel<<<40, 256>>>(W1, W2, W3, d_w1h, d_w1l, d_w2h, d_w2l, d_w3h, d_w3l);  // 0
    zero_cnt_kernel<<<nb, 256>>>(d_cnt, n);                                            // 1
    count_kernel<<<(E + 255) / 256, 256>>>(d_cnt, dst, E);                             // 2
    gemm_mma_kernel<128, false><<<gemm_blocks, 256, SMEM_A>>>(x, d_w1h, d_w1l, d_h, n);// 3 (profiled)
    scan1_kernel<<<nb, 256>>>(d_cnt, d_cursor, d_bsums, d_dis, n);                     // 4
    scan2_kernel<<<1, 1024>>>(d_bsums, nb);                                            // 5
    scan3_kernel<<<nb, 256>>>(d_cursor, d_bsums, d_rowptr, d_cursor, n, E);            // 6
    fill_kernel<<<(E + 255) / 256, 256>>>(src, dst, d_dis, d_cursor, d_esrc, d_ewt, E);// 7

    // Layer 1 aggregate
    agg_kernel<128><<<agg128_blocks, 256>>>(d_rowptr, d_esrc, d_ewt, d_h, d_dis, b1, d_bufA, n);

    // Layer 2
    gemm_mma_kernel<128, true><<<gemm_blocks, 256, SMEM_A>>>(d_bufA, d_w2h, d_w2l, d_h, n);
    agg_kernel<128><<<agg128_blocks, 256>>>(d_rowptr, d_esrc, d_ewt, d_h, d_dis, b2, d_bufB, n);

    // Layer 3 (DOUT=64)
    gemm_mma_kernel<64, true><<<gemm_blocks, 256, SMEM_A>>>(d_bufB, d_w3h, d_w3l, d_h, n);
    agg_kernel<64><<<agg64_blocks, 256>>>(d_rowptr, d_esrc, d_ewt, d_h, d_dis, b3, d_bufA, n);

    // Decode
    decode_kernel<<<((EL * 16) + 255) / 256, 256>>>(d_bufA, eli, out_hidden, out_logits, EL);
}